// round 7
// baseline (speedup 1.0000x reference)
#include <cuda_runtime.h>
#include <math.h>

// Problem constants (fixed shapes)
#define BB 64      // batch
#define TT 512     // time / bucket_size
#define NU 256     // units
#define N3 768     // 3*units
#define LN_EPS 1e-5f

typedef unsigned long long ull;
typedef unsigned int uint;

// ---------------- scratch (static device arrays; no runtime allocation) ----
__device__ float g_xemb[TT * BB * NU];   // [t][b][c]   33.5 MB
__device__ float g_s1[TT * BB * N3];     // [t][b][768] 100 MB (LN'd in place)
__device__ uint  g_enc[BB * NU];         // encoded running max for conv

// ---------------- small helpers -------------------------------------------
__device__ __forceinline__ uint enc_f(float v) {
    uint u = __float_as_uint(v);
    return ((int)u < 0) ? ~u : (u | 0x80000000u);
}
__device__ __forceinline__ float dec_f(uint e) {
    uint u = (e & 0x80000000u) ? (e ^ 0x80000000u) : ~e;
    return __uint_as_float(u);
}
__device__ __forceinline__ float hsig(float v) {
    return fminf(fmaxf(0.2f * v + 0.5f, 0.0f), 1.0f);
}
__device__ __forceinline__ float2 ull2f2(ull v) {
    float2 r;
    asm("mov.b64 {%0, %1}, %2;" : "=f"(r.x), "=f"(r.y) : "l"(v));
    return r;
}
__device__ __forceinline__ ull f22ull(float2 v) {
    ull r;
    asm("mov.b64 %0, {%1, %2};" : "=l"(r) : "f"(v.x), "f"(v.y));
    return r;
}
// packed fma: acc.{lo,hi} += hk.{lo,hi} * u
#define FMA2(acc, hk, uval) do {                                          \
    ull _pu;                                                              \
    asm("mov.b64 %0, {%1, %1};" : "=l"(_pu) : "f"(uval));                 \
    asm("fma.rn.f32x2 %0, %1, %2, %0;" : "+l"(acc) : "l"(hk), "l"(_pu));  \
} while (0)

__device__ __forceinline__ uint ctarank() {
    uint r; asm("mov.u32 %0, %%cluster_ctarank;" : "=r"(r)); return r;
}
__device__ __forceinline__ void st_cl_b64(void* laddr, uint r, ull v) {
    uint la = (uint)__cvta_generic_to_shared(laddr);
    asm volatile(
        "{ .reg .b32 ra; mapa.shared::cluster.u32 ra, %0, %1; "
        "st.shared::cluster.b64 [ra], %2; }"
        :: "r"(la), "r"(r), "l"(v) : "memory");
}
#define CLUSTER_SYNC() do {                                        \
    asm volatile("barrier.cluster.arrive.aligned;" ::: "memory");  \
    asm volatile("barrier.cluster.wait.aligned;" ::: "memory");    \
} while (0)

// mbarrier helpers (cluster-scope release/acquire)
__device__ __forceinline__ void mbar_init(void* bar, uint cnt) {
    uint a = (uint)__cvta_generic_to_shared(bar);
    asm volatile("mbarrier.init.shared.b64 [%0], %1;" :: "r"(a), "r"(cnt)
                 : "memory");
}
__device__ __forceinline__ void mbar_arrive_rank(void* bar, uint r) {
    uint la = (uint)__cvta_generic_to_shared(bar);
    asm volatile(
        "{ .reg .b32 ra; mapa.shared::cluster.u32 ra, %0, %1; "
        "mbarrier.arrive.release.cluster.shared::cluster.b64 _, [ra]; }"
        :: "r"(la), "r"(r) : "memory");
}
__device__ __forceinline__ void mbar_wait(void* bar, uint parity) {
    uint a = (uint)__cvta_generic_to_shared(bar);
    uint done;
    asm volatile(
        "{ .reg .pred p; "
        "mbarrier.try_wait.parity.acquire.cluster.shared::cta.b64 p, [%1], %2; "
        "selp.b32 %0, 1, 0, p; }"
        : "=r"(done) : "r"(a), "r"(parity) : "memory");
    if (!done) {
        asm volatile(
            "{ .reg .pred P1; "
            "W%=: mbarrier.try_wait.parity.acquire.cluster.shared::cta.b64 P1, [%0], %1, 0x989680; "
            "@P1 bra D%=; bra W%=; D%=: }"
            :: "r"(a), "r"(parity) : "memory");
    }
}

__device__ __forceinline__ uint f2tf32(float v) {
    uint r;
    asm("cvt.rna.tf32.f32 %0, %1;" : "=r"(r) : "f"(v));
    return r;
}

// ---------------- embedding gather ----------------------------------------
__global__ void embed_kernel(const int* __restrict__ x,
                             const float* __restrict__ emb) {
    int idx = blockIdx.x * 256 + threadIdx.x;
    int c = idx & 255;
    int b = (idx >> 8) & 63;
    int t = idx >> 14;
    int row = x[(size_t)b * TT + t];
    g_xemb[idx] = emb[(size_t)row * NU + c];
}

__global__ void encinit_kernel() {
    g_enc[blockIdx.x * 256 + threadIdx.x] = enc_f(-INFINITY);
}
__global__ void decode_kernel(float* __restrict__ out) {
    int f = threadIdx.x;           // 256
    int b = blockIdx.x;            // 64
    out[(size_t)b * 512 + 256 + f] = dec_f(g_enc[b * 256 + f]);
}

// ---------------- 128x128 3xTF32 tensor-core GEMM --------------------------
// C(MxN) = A(MxK) * B(KxN) at ~fp32 accuracy: A,B split into tf32 hi + lo
// residual; acc += Ahi*Bhi + Alo*Bhi + Ahi*Blo (dropped lo*lo term ~1e-8).
// A uses g_xemb segment addressing:
//   A[row,k] = A[row*256 + (k>>8)*16384 + (k&255)]  (row-major when K=256;
//   realizes the width-3 conv as one GEMM when K=768).
// BK=16, 256 threads = 8 warps (2 m x 4 n), warp tile 64x32 via m16n8k8.
// smem k-major, stride 136 (= 8 mod 32 banks -> conflict-free frags).
#define TSTR 136
#define GTILE (16 * TSTR)
__global__ void __launch_bounds__(256)
gemm_tc(const float* __restrict__ A, const float* __restrict__ B,
        const float* __restrict__ bias, float* __restrict__ C,
        int N, int K, int domax) {
    extern __shared__ uint dsm[];
    uint* AsH = dsm;                 // [2][GTILE]
    uint* AsL = dsm + 2 * GTILE;
    uint* BsH = dsm + 4 * GTILE;
    uint* BsL = dsm + 6 * GTILE;

    int tid = threadIdx.x;
    int lane = tid & 31, warp = tid >> 5;
    int wm = warp >> 2, wn = warp & 3;           // warp grid 2x4
    int lk = lane & 3, lg = lane >> 2;
    int r0 = blockIdx.y * 128, c0 = blockIdx.x * 128;

    // staging roles
    int am = tid >> 1, akq = (tid & 1) * 8;      // A: row am, 8 k's
    int bk = tid >> 4, bn = (tid & 15) * 8;      // B: k row bk, 8 n's

    float c[4][4][4];
    #pragma unroll
    for (int i = 0; i < 4; i++)
        #pragma unroll
        for (int j = 0; j < 4; j++)
            #pragma unroll
            for (int q = 0; q < 4; q++) c[i][j][q] = 0.0f;

    const float* Arow = A + (size_t)(r0 + am) * 256;

    float aL[8], bL[8];
    {   // prefetch tile 0
        int fk = akq;
        int ab = ((fk >> 8) << 14) + (fk & 255);
        float4 v0 = *(const float4*)&Arow[ab];
        float4 v1 = *(const float4*)&Arow[ab + 4];
        aL[0]=v0.x; aL[1]=v0.y; aL[2]=v0.z; aL[3]=v0.w;
        aL[4]=v1.x; aL[5]=v1.y; aL[6]=v1.z; aL[7]=v1.w;
        const float* Bp = &B[(size_t)bk * N + c0 + bn];
        float4 w0 = *(const float4*)Bp;
        float4 w1 = *(const float4*)(Bp + 4);
        bL[0]=w0.x; bL[1]=w0.y; bL[2]=w0.z; bL[3]=w0.w;
        bL[4]=w1.x; bL[5]=w1.y; bL[6]=w1.z; bL[7]=w1.w;
        #pragma unroll
        for (int i = 0; i < 8; i++) {
            uint ah = f2tf32(aL[i]);
            uint bh = f2tf32(bL[i]);
            AsH[(akq + i) * TSTR + am] = ah;
            AsL[(akq + i) * TSTR + am] = f2tf32(aL[i] - __uint_as_float(ah));
            BsH[bk * TSTR + bn + i] = bh;
            BsL[bk * TSTR + bn + i] = f2tf32(bL[i] - __uint_as_float(bh));
        }
    }
    __syncthreads();

    int buf = 0;
    for (int k0 = 0; k0 < K; k0 += 16) {
        bool more = (k0 + 16) < K;
        if (more) {
            int fk = k0 + 16 + akq;
            int ab = ((fk >> 8) << 14) + (fk & 255);
            float4 v0 = *(const float4*)&Arow[ab];
            float4 v1 = *(const float4*)&Arow[ab + 4];
            aL[0]=v0.x; aL[1]=v0.y; aL[2]=v0.z; aL[3]=v0.w;
            aL[4]=v1.x; aL[5]=v1.y; aL[6]=v1.z; aL[7]=v1.w;
            const float* Bp = &B[(size_t)(k0 + 16 + bk) * N + c0 + bn];
            float4 w0 = *(const float4*)Bp;
            float4 w1 = *(const float4*)(Bp + 4);
            bL[0]=w0.x; bL[1]=w0.y; bL[2]=w0.z; bL[3]=w0.w;
            bL[4]=w1.x; bL[5]=w1.y; bL[6]=w1.z; bL[7]=w1.w;
        }
        const uint* asH = AsH + buf * GTILE;
        const uint* asL = AsL + buf * GTILE;
        const uint* bsH = BsH + buf * GTILE;
        const uint* bsL = BsL + buf * GTILE;
        #pragma unroll
        for (int kt = 0; kt < 2; kt++) {
            int kb = kt * 8;
            uint afH[4][4], afL[4][4], bfH[4][2], bfL[4][2];
            #pragma unroll
            for (int mt = 0; mt < 4; mt++) {
                int m = wm * 64 + mt * 16 + lg;
                int i0 = (kb + lk) * TSTR + m, i1 = (kb + lk + 4) * TSTR + m;
                afH[mt][0] = asH[i0];     afH[mt][1] = asH[i0 + 8];
                afH[mt][2] = asH[i1];     afH[mt][3] = asH[i1 + 8];
                afL[mt][0] = asL[i0];     afL[mt][1] = asL[i0 + 8];
                afL[mt][2] = asL[i1];     afL[mt][3] = asL[i1 + 8];
            }
            #pragma unroll
            for (int nt = 0; nt < 4; nt++) {
                int n = wn * 32 + nt * 8 + lg;
                bfH[nt][0] = bsH[(kb + lk) * TSTR + n];
                bfH[nt][1] = bsH[(kb + lk + 4) * TSTR + n];
                bfL[nt][0] = bsL[(kb + lk) * TSTR + n];
                bfL[nt][1] = bsL[(kb + lk + 4) * TSTR + n];
            }
            #pragma unroll
            for (int mt = 0; mt < 4; mt++)
                #pragma unroll
                for (int nt = 0; nt < 4; nt++) {
                    asm("mma.sync.aligned.m16n8k8.row.col.f32.tf32.tf32.f32 "
                        "{%0,%1,%2,%3}, {%4,%5,%6,%7}, {%8,%9}, {%0,%1,%2,%3};"
                        : "+f"(c[mt][nt][0]), "+f"(c[mt][nt][1]),
                          "+f"(c[mt][nt][2]), "+f"(c[mt][nt][3])
                        : "r"(afL[mt][0]), "r"(afL[mt][1]),
                          "r"(afL[mt][2]), "r"(afL[mt][3]),
                          "r"(bfH[nt][0]), "r"(bfH[nt][1]));
                    asm("mma.sync.aligned.m16n8k8.row.col.f32.tf32.tf32.f32 "
                        "{%0,%1,%2,%3}, {%4,%5,%6,%7}, {%8,%9}, {%0,%1,%2,%3};"
                        : "+f"(c[mt][nt][0]), "+f"(c[mt][nt][1]),
                          "+f"(c[mt][nt][2]), "+f"(c[mt][nt][3])
                        : "r"(afH[mt][0]), "r"(afH[mt][1]),
                          "r"(afH[mt][2]), "r"(afH[mt][3]),
                          "r"(bfL[nt][0]), "r"(bfL[nt][1]));
                    asm("mma.sync.aligned.m16n8k8.row.col.f32.tf32.tf32.f32 "
                        "{%0,%1,%2,%3}, {%4,%5,%6,%7}, {%8,%9}, {%0,%1,%2,%3};"
                        : "+f"(c[mt][nt][0]), "+f"(c[mt][nt][1]),
                          "+f"(c[mt][nt][2]), "+f"(c[mt][nt][3])
                        : "r"(afH[mt][0]), "r"(afH[mt][1]),
                          "r"(afH[mt][2]), "r"(afH[mt][3]),
                          "r"(bfH[nt][0]), "r"(bfH[nt][1]));
                }
        }
        if (more) {
            uint* aH = AsH + (buf ^ 1) * GTILE;
            uint* aLo = AsL + (buf ^ 1) * GTILE;
            uint* bH = BsH + (buf ^ 1) * GTILE;
            uint* bLo = BsL + (buf ^ 1) * GTILE;
            #pragma unroll
            for (int i = 0; i < 8; i++) {
                uint ah = f2tf32(aL[i]);
                uint bh = f2tf32(bL[i]);
                aH[(akq + i) * TSTR + am] = ah;
                aLo[(akq + i) * TSTR + am] = f2tf32(aL[i] - __uint_as_float(ah));
                bH[bk * TSTR + bn + i] = bh;
                bLo[bk * TSTR + bn + i] = f2tf32(bL[i] - __uint_as_float(bh));
            }
        }
        __syncthreads();
        buf ^= 1;
    }

    // epilogue: c0,c1 at (row lg, cols 2*lk, 2*lk+1); c2,c3 at row lg+8
    #pragma unroll
    for (int mt = 0; mt < 4; mt++) {
        #pragma unroll
        for (int nt = 0; nt < 4; nt++) {
            int row0 = r0 + wm * 64 + mt * 16 + lg;
            int col  = c0 + wn * 32 + nt * 8 + lk * 2;
            float v0 = c[mt][nt][0], v1 = c[mt][nt][1];
            float v2 = c[mt][nt][2], v3 = c[mt][nt][3];
            if (bias) {
                float bb0 = bias[col], bb1 = bias[col + 1];
                v0 += bb0; v1 += bb1; v2 += bb0; v3 += bb1;
            }
            if (C) {
                *(float2*)&C[(size_t)row0 * N + col] = make_float2(v0, v1);
                *(float2*)&C[(size_t)(row0 + 8) * N + col] = make_float2(v2, v3);
            }
            if (domax) {
                int ba = row0 & 63, bb = (row0 + 8) & 63;
                atomicMax(&g_enc[ba * 256 + col], enc_f(v0));
                atomicMax(&g_enc[ba * 256 + col + 1], enc_f(v1));
                atomicMax(&g_enc[bb * 256 + col], enc_f(v2));
                atomicMax(&g_enc[bb * 256 + col + 1], enc_f(v3));
            }
        }
    }
}

// ---------------- row LayerNorm over 768 cols, in place on g_s1 ------------
__global__ void ln_kernel(const float* __restrict__ gam,
                          const float* __restrict__ bet) {
    int row = blockIdx.x;
    float* p = g_s1 + (size_t)row * N3;
    int tid = threadIdx.x;
    float v0 = p[tid], v1 = p[tid + 256], v2 = p[tid + 512];
    float s = v0 + v1 + v2;
    float q = v0 * v0 + v1 * v1 + v2 * v2;
    __shared__ float rs[8], rq[8];
    __shared__ float tot[2];
    int lane = tid & 31, w = tid >> 5;
    #pragma unroll
    for (int o = 16; o; o >>= 1) {
        s += __shfl_down_sync(0xffffffffu, s, o);
        q += __shfl_down_sync(0xffffffffu, q, o);
    }
    if (!lane) { rs[w] = s; rq[w] = q; }
    __syncthreads();
    if (tid == 0) {
        float S = 0, Q = 0;
        for (int i = 0; i < 8; i++) { S += rs[i]; Q += rq[i]; }
        tot[0] = S; tot[1] = Q;
    }
    __syncthreads();
    float mean = tot[0] * (1.0f / 768.0f);
    float var = fmaxf(tot[1] * (1.0f / 768.0f) - mean * mean, 0.0f);
    float inv = 1.0f / (sqrtf(var + LN_EPS) + LN_EPS);
    p[tid]       = gam[tid]       * ((v0 - mean) * inv) + bet[tid];
    p[tid + 256] = gam[tid + 256] * ((v1 - mean) * inv) + bet[tid + 256];
    p[tid + 512] = gam[tid + 512] * ((v2 - mean) * inv) + bet[tid + 512];
}

// =============== recurrence: 32 clusters x 4 CTAs, U in REGISTERS ==========
// Sync via mbarriers (arrive.release.cluster / try_wait.acquire.cluster),
// parity = t&1. bA: 4 arrivals (tid0 per rank). bB: 512 (128 producers x 4
// ranks). bC: 256 (64 producers x 4 ranks).
__global__ void __launch_bounds__(256, 1) __cluster_dims__(4, 1, 1)
rec_kernel(const int* __restrict__ x, const float* __restrict__ Umat,
           const float* __restrict__ s1, const float* __restrict__ gammas,
           const float* __restrict__ betas, float* __restrict__ out) {
    __shared__ __align__(16) float2 h2[256];    // h, local authoritative copy
    __shared__ __align__(16) float2 rh2[256];   // r*h (cluster-broadcast)
    __shared__ __align__(16) float2 z2g[256];   // z gates (cluster-broadcast)
    __shared__ __align__(16) float2 sBg[256];   // hc presums (cluster-broadcast)
    __shared__ __align__(16) float2 cbuf[192];  // intra-CTA partial exchange
    __shared__ float2 wsl[8];                   // warp reduction slots
    __shared__ float2 pA[8];                    // LN-A partials per rank (S,Q)
    __shared__ float2 pB[8];                    // LN-B partials per rank (S,Q)
    __shared__ __align__(8) ull barA, barB, barC;

    int tid  = threadIdx.x;
    uint rank = ctarank();
    int cid  = blockIdx.x >> 2;
    int b0   = cid * 2, b1 = b0 + 1;
    int lane = tid & 31, wid = tid >> 5;

    int colA  = tid & 127;
    int khalf = tid >> 7;
    int gA = (colA < 64) ? ((int)rank * 64 + colA)
                         : (256 + (int)rank * 64 + (colA - 64));
    float g1a = gammas[N3 + gA], be1a = betas[N3 + gA];
    int uC = tid;                                 // phase-C unit (0..255)
    float g1c = gammas[N3 + 512 + uC], be1c = betas[N3 + 512 + uC];
    int uB = tid & 63, kq = tid >> 6;
    int gB = (int)rank * 64 + uB;

    // ---- one-time: U slices into registers ----
    float UA[128];
    #pragma unroll
    for (int k = 0; k < 128; k++)
        UA[k] = Umat[(size_t)(khalf * 128 + k) * N3 + gA];
    float UB[64];
    #pragma unroll
    for (int j = 0; j < 64; j++)
        UB[j] = Umat[(size_t)(kq * 64 + j) * N3 + 512 + gB];

    h2[tid] = make_float2(0.0f, 0.0f);
    if (tid == 0) {
        mbar_init(&barA, 4);
        mbar_init(&barB, 512);
        mbar_init(&barC, 256);
    }
    __syncthreads();
    CLUSTER_SYNC();   // peers' smem + barriers initialized

    for (int t = 0; t < TT; t++) {
        uint par = (uint)(t & 1);
        // prefetch s1 / masks (consumed late)
        const float* s1r0 = s1 + ((size_t)t * 64 + b0) * N3;
        const float* s1r1 = s1r0 + N3;
        float s1a0 = 0.0f, s1a1 = 0.0f;
        if (tid < 128) { s1a0 = s1r0[gA]; s1a1 = s1r1[gA]; }
        float s1c0 = s1r0[512 + uC], s1c1 = s1r1[512 + uC];
        int m0 = x[(size_t)b0 * TT + t], m1 = x[(size_t)b1 * TT + t];

        // ---- phase A: h @ U[:, gA] over k-half (U in regs, h broadcast) --
        const ull* hp = (const ull*)h2 + khalf * 128;
        ull a0 = 0, a1 = 0, a2 = 0, a3 = 0;
        #pragma unroll
        for (int k = 0; k < 128; k += 4) {
            ulonglong2 ha = *(const ulonglong2*)(hp + k);
            ulonglong2 hb = *(const ulonglong2*)(hp + k + 2);
            FMA2(a0, ha.x, UA[k]);     FMA2(a1, ha.y, UA[k + 1]);
            FMA2(a2, hb.x, UA[k + 2]); FMA2(a3, hb.y, UA[k + 3]);
        }
        float2 f0 = ull2f2(a0), f1 = ull2f2(a1);
        float2 f2v = ull2f2(a2), f3 = ull2f2(a3);
        float2 accA = make_float2((f0.x + f1.x) + (f2v.x + f3.x),
                                  (f0.y + f1.y) + (f2v.y + f3.y));
        if (tid >= 128) cbuf[tid - 128] = accA;
        __syncthreads();

        float2 sval = make_float2(0.0f, 0.0f);
        if (tid < 128) {
            float2 oth = cbuf[tid];
            sval.x = accA.x + oth.x; sval.y = accA.y + oth.y;
            float p0 = sval.x, p1 = sval.y;
            float q0 = p0 * p0, q1 = p1 * p1;
            #pragma unroll
            for (int o = 16; o; o >>= 1) {
                p0 += __shfl_down_sync(0xffffffffu, p0, o);
                p1 += __shfl_down_sync(0xffffffffu, p1, o);
                q0 += __shfl_down_sync(0xffffffffu, q0, o);
                q1 += __shfl_down_sync(0xffffffffu, q1, o);
            }
            if (!lane) { wsl[wid] = make_float2(p0, p1);
                         wsl[4 + wid] = make_float2(q0, q1); }
        }
        __syncthreads();
        if (tid == 0) {
            float2 S = make_float2(0, 0), Q = make_float2(0, 0);
            #pragma unroll
            for (int w = 0; w < 4; w++) {
                S.x += wsl[w].x; S.y += wsl[w].y;
                Q.x += wsl[4 + w].x; Q.y += wsl[4 + w].y;
            }
            #pragma unroll
            for (uint r = 0; r < 4; r++) {
                st_cl_b64(&pA[rank], r, f22ull(S));
                st_cl_b64(&pA[4 + rank], r, f22ull(Q));
            }
            #pragma unroll
            for (uint r = 0; r < 4; r++) mbar_arrive_rank(&barA, r);
        }
        mbar_wait(&barA, par);   // S1: LN-A partials visible everywhere

        // ---- gate: z broadcast, rh broadcast ----
        if (tid < 128) {
            float2 S = make_float2(0, 0), Q = make_float2(0, 0);
            #pragma unroll
            for (int r = 0; r < 4; r++) {
                S.x += pA[r].x; S.y += pA[r].y;
                Q.x += pA[4 + r].x; Q.y += pA[4 + r].y;
            }
            float mean0 = S.x * (1.0f / 512.0f), mean1 = S.y * (1.0f / 512.0f);
            float var0 = fmaxf(Q.x * (1.0f / 512.0f) - mean0 * mean0, 0.0f);
            float var1 = fmaxf(Q.y * (1.0f / 512.0f) - mean1 * mean1, 0.0f);
            float inv0 = 1.0f / (sqrtf(var0 + LN_EPS) + LN_EPS);
            float inv1 = 1.0f / (sqrtf(var1 + LN_EPS) + LN_EPS);
            float sv0 = hsig(s1a0 + g1a * ((sval.x - mean0) * inv0) + be1a);
            float sv1 = hsig(s1a1 + g1a * ((sval.y - mean1) * inv1) + be1a);
            if (colA < 64) {
                int gz = (int)rank * 64 + colA;
                ull pv = f22ull(make_float2(sv0, sv1));
                #pragma unroll
                for (uint r = 0; r < 4; r++) st_cl_b64(&z2g[gz], r, pv);
            } else {
                int uu = (int)rank * 64 + colA - 64;
                float2 h = h2[uu];
                ull pv = f22ull(make_float2(sv0 * h.x, sv1 * h.y));
                #pragma unroll
                for (uint r = 0; r < 4; r++) st_cl_b64(&rh2[uu], r, pv);
            }
            #pragma unroll
            for (uint r = 0; r < 4; r++) mbar_arrive_rank(&barB, r);
        }
        mbar_wait(&barB, par);   // S2: rh + z visible everywhere

        // ---- phase B: (r*h) @ U[:, 512+gB] over k-quarter ----
        const ull* rp = (const ull*)rh2 + kq * 64;
        ull b0a = 0, b1a = 0;
        #pragma unroll
        for (int j = 0; j < 64; j += 4) {
            ulonglong2 ra = *(const ulonglong2*)(rp + j);
            ulonglong2 rb = *(const ulonglong2*)(rp + j + 2);
            FMA2(b0a, ra.x, UB[j]);     FMA2(b1a, ra.y, UB[j + 1]);
            FMA2(b0a, rb.x, UB[j + 2]); FMA2(b1a, rb.y, UB[j + 3]);
        }
        float2 g0 = ull2f2(b0a), g1 = ull2f2(b1a);
        float2 accB = make_float2(g0.x + g1.x, g0.y + g1.y);
        if (tid >= 64) cbuf[tid - 64] = accB;
        __syncthreads();

        if (tid < 64) {
            float2 o1 = cbuf[tid], o2 = cbuf[64 + tid], o3 = cbuf[128 + tid];
            float2 sB = make_float2(accB.x + o1.x + o2.x + o3.x,
                                    accB.y + o1.y + o2.y + o3.y);
            ull pv = f22ull(sB);
            #pragma unroll
            for (uint r = 0; r < 4; r++) st_cl_b64(&sBg[gB], r, pv);
            float p0 = sB.x, p1 = sB.y, q0 = p0 * p0, q1 = p1 * p1;
            #pragma unroll
            for (int o = 16; o; o >>= 1) {
                p0 += __shfl_down_sync(0xffffffffu, p0, o);
                p1 += __shfl_down_sync(0xffffffffu, p1, o);
                q0 += __shfl_down_sync(0xffffffffu, q0, o);
                q1 += __shfl_down_sync(0xffffffffu, q1, o);
            }
            if (!lane) { wsl[wid] = make_float2(p0, p1);
                         wsl[4 + wid] = make_float2(q0, q1); }
        }
        __syncthreads();
        if (tid < 64) {
            if (tid == 0) {
                float2 S = make_float2(wsl[0].x + wsl[1].x, wsl[0].y + wsl[1].y);
                float2 Q = make_float2(wsl[4].x + wsl[5].x, wsl[4].y + wsl[5].y);
                #pragma unroll
                for (uint r = 0; r < 4; r++) {
                    st_cl_b64(&pB[rank], r, f22ull(S));
                    st_cl_b64(&pB[4 + rank], r, f22ull(Q));
                }
            }
            #pragma unroll
            for (uint r = 0; r < 4; r++) mbar_arrive_rank(&barC, r);
        }
        mbar_wait(&barC, par);   // S3: sB + LN-B partials visible everywhere

        // ---- phase C: computed redundantly by ALL CTAs; h stays local ----
        {
            float2 S = make_float2(0, 0), Q = make_float2(0, 0);
            #pragma unroll
            for (int r = 0; r < 4; r++) {
                S.x += pB[r].x; S.y += pB[r].y;
                Q.x += pB[4 + r].x; Q.y += pB[4 + r].y;
            }
            float mean0 = S.x * (1.0f / 256.0f), mean1 = S.y * (1.0f / 256.0f);
            float var0 = fmaxf(Q.x * (1.0f / 256.0f) - mean0 * mean0, 0.0f);
            float var1 = fmaxf(Q.y * (1.0f / 256.0f) - mean1 * mean1, 0.0f);
            float inv0 = 1.0f / (sqrtf(var0 + LN_EPS) + LN_EPS);
            float inv1 = 1.0f / (sqrtf(var1 + LN_EPS) + LN_EPS);
            float2 sB = sBg[uC];
            float hc0 = tanhf(s1c0 + g1c * ((sB.x - mean0) * inv0) + be1c);
            float hc1 = tanhf(s1c1 + g1c * ((sB.y - mean1) * inv1) + be1c);
            float2 z = z2g[uC];
            float2 h = h2[uC];
            float hn0 = z.x * h.x + (1.0f - z.x) * hc0;
            float hn1 = z.y * h.y + (1.0f - z.y) * hc1;
            h2[uC] = make_float2(m0 ? hn0 : h.x, m1 ? hn1 : h.y);
        }
        __syncthreads();   // h2 complete before next phase A (CTA-local)
    }

    if (rank == 0) {
        float2 h = h2[uC];
        out[(size_t)b0 * 512 + uC] = h.x;
        out[(size_t)b1 * 512 + uC] = h.y;
    }
    CLUSTER_SYNC();   // no CTA exits while peers may still remote-access
}

// ---------------- launch ---------------------------------------------------
extern "C" void kernel_launch(void* const* d_in, const int* in_sizes, int n_in,
                              void* d_out, int out_size) {
    const int* x           = (const int*)d_in[0];   // token ids (int32)
    const float* emb       = (const float*)d_in[2];
    const float* W         = (const float*)d_in[3];
    const float* Umat      = (const float*)d_in[4];
    const float* bias      = (const float*)d_in[5];
    const float* gammas    = (const float*)d_in[6];
    const float* betas     = (const float*)d_in[7];
    const float* kern      = (const float*)d_in[8];
    float* out             = (float*)d_out;

    float *xe, *s1p;
    cudaGetSymbolAddress((void**)&xe, g_xemb);
    cudaGetSymbolAddress((void**)&s1p, g_s1);

    const int gsm = 8 * GTILE * (int)sizeof(uint);   // 69632 B
    cudaFuncSetAttribute(gemm_tc, cudaFuncAttributeMaxDynamicSharedMemorySize,
                         gsm);

    // 1) embedding gather
    embed_kernel<<<TT * BB, 256>>>(x, emb);
    // 2) s1 = x_emb @ W + b  (M=32768, N=768, K=256), then LN in place
    gemm_tc<<<dim3(N3 / 128, TT * BB / 128), 256, gsm>>>(xe, W, bias, s1p,
                                                         N3, NU, 0);
    ln_kernel<<<TT * BB, 256>>>(gammas, betas);
    // 3) conv as ONE K=768 GEMM (M = 510*64 = 32640 = 255*128) with fused max
    encinit_kernel<<<BB, 256>>>();
    gemm_tc<<<dim3(NU / 128, (510 * BB) / 128), 256, gsm>>>(xe, kern, nullptr,
                                                            nullptr, NU,
                                                            3 * NU, 1);
    decode_kernel<<<BB, 256>>>(out);
    // 4) recurrence: cluster-parallel, U register-resident, mbarrier sync
    rec_kernel<<<128, 256>>>(x, Umat, s1p, gammas, betas, out);
}

// round 10
// speedup vs baseline: 1.2589x; 1.2589x over previous
#include <cuda_runtime.h>
#include <math.h>

// Problem constants (fixed shapes)
#define BB 64      // batch
#define TT 512     // time / bucket_size
#define NU 256     // units
#define N3 768     // 3*units
#define LN_EPS 1e-5f

typedef unsigned long long ull;
typedef unsigned int uint;

// ---------------- scratch (static device arrays; no runtime allocation) ----
__device__ float g_xemb[TT * BB * NU];   // [t][b][c]   33.5 MB
__device__ float g_s1[TT * BB * N3];     // [t][b][768] 100 MB (LN'd in place)
__device__ uint  g_enc[BB * NU];         // encoded running max for conv

// ---------------- small helpers -------------------------------------------
__device__ __forceinline__ uint enc_f(float v) {
    uint u = __float_as_uint(v);
    return ((int)u < 0) ? ~u : (u | 0x80000000u);
}
__device__ __forceinline__ float dec_f(uint e) {
    uint u = (e & 0x80000000u) ? (e ^ 0x80000000u) : ~e;
    return __uint_as_float(u);
}
__device__ __forceinline__ float hsig(float v) {
    return fminf(fmaxf(0.2f * v + 0.5f, 0.0f), 1.0f);
}
__device__ __forceinline__ float2 ull2f2(ull v) {
    float2 r;
    asm("mov.b64 {%0, %1}, %2;" : "=f"(r.x), "=f"(r.y) : "l"(v));
    return r;
}
__device__ __forceinline__ ull f22ull(float2 v) {
    ull r;
    asm("mov.b64 %0, {%1, %2};" : "=l"(r) : "f"(v.x), "f"(v.y));
    return r;
}
// packed fma: acc.{lo,hi} += hk.{lo,hi} * u
#define FMA2(acc, hk, uval) do {                                          \
    ull _pu;                                                              \
    asm("mov.b64 %0, {%1, %1};" : "=l"(_pu) : "f"(uval));                 \
    asm("fma.rn.f32x2 %0, %1, %2, %0;" : "+l"(acc) : "l"(hk), "l"(_pu));  \
} while (0)

__device__ __forceinline__ uint ctarank() {
    uint r; asm("mov.u32 %0, %%cluster_ctarank;" : "=r"(r)); return r;
}
__device__ __forceinline__ void st_cl_b64(void* laddr, uint r, ull v) {
    uint la = (uint)__cvta_generic_to_shared(laddr);
    asm volatile(
        "{ .reg .b32 ra; mapa.shared::cluster.u32 ra, %0, %1; "
        "st.shared::cluster.b64 [ra], %2; }"
        :: "r"(la), "r"(r), "l"(v) : "memory");
}
#define CLUSTER_SYNC() do {                                        \
    asm volatile("barrier.cluster.arrive.aligned;" ::: "memory");  \
    asm volatile("barrier.cluster.wait.aligned;" ::: "memory");    \
} while (0)

__device__ __forceinline__ uint f2tf32(float v) {
    uint r;
    asm("cvt.rna.tf32.f32 %0, %1;" : "=r"(r) : "f"(v));
    return r;
}

// ---------------- embedding gather ----------------------------------------
__global__ void embed_kernel(const int* __restrict__ x,
                             const float* __restrict__ emb) {
    int idx = blockIdx.x * 256 + threadIdx.x;
    int c = idx & 255;
    int b = (idx >> 8) & 63;
    int t = idx >> 14;
    int row = x[(size_t)b * TT + t];
    g_xemb[idx] = emb[(size_t)row * NU + c];
}

__global__ void encinit_kernel() {
    g_enc[blockIdx.x * 256 + threadIdx.x] = enc_f(-INFINITY);
}
__global__ void decode_kernel(float* __restrict__ out) {
    int f = threadIdx.x;           // 256
    int b = blockIdx.x;            // 64
    out[(size_t)b * 512 + 256 + f] = dec_f(g_enc[b * 256 + f]);
}

// ---------------- 128x128 3xTF32 tensor-core GEMM --------------------------
// C(MxN) = A(MxK) * B(KxN) at ~fp32 accuracy: hi/lo tf32 split, 3 MMAs
// (AhiBhi + AloBhi + AhiBlo). hi and lo live INTERLEAVED as uint2 in smem so
// one LDS.64 / STS.64 moves both -> same LDS/STS count as 1-pass tf32.
// A uses g_xemb segment addressing:
//   A[row,k] = A[row*256 + (k>>8)*16384 + (k&255)]  (row-major when K=256;
//   realizes the width-3 conv as one GEMM when K=768).
// BK=16, 256 threads = 8 warps (2 m x 4 n), warp tile 64x32 via m16n8k8.
// smem k-major uint2, stride 132 (row shift = 8 banks -> conflict-free).
#define AST2 132
#define GT2 (16 * AST2)     // uint2 per tile
__global__ void __launch_bounds__(256)
gemm_tc(const float* __restrict__ A, const float* __restrict__ B,
        const float* __restrict__ bias, float* __restrict__ C,
        int N, int K, int domax) {
    extern __shared__ uint2 dsm2[];
    uint2* As2 = dsm2;               // [2][GT2]
    uint2* Bs2 = dsm2 + 2 * GT2;     // [2][GT2]

    int tid = threadIdx.x;
    int lane = tid & 31, warp = tid >> 5;
    int wm = warp >> 2, wn = warp & 3;           // warp grid 2x4
    int lk = lane & 3, lg = lane >> 2;
    int r0 = blockIdx.y * 128, c0 = blockIdx.x * 128;

    // staging roles
    int am = tid >> 1, akq = (tid & 1) * 8;      // A: row am, 8 k's
    int bk = tid >> 4, bn = (tid & 15) * 8;      // B: k row bk, 8 n's

    float c[4][4][4];
    #pragma unroll
    for (int i = 0; i < 4; i++)
        #pragma unroll
        for (int j = 0; j < 4; j++)
            #pragma unroll
            for (int q = 0; q < 4; q++) c[i][j][q] = 0.0f;

    const float* Arow = A + (size_t)(r0 + am) * 256;

    float aL[8], bL[8];
    {   // prefetch tile 0
        int fk = akq;
        int ab = ((fk >> 8) << 14) + (fk & 255);
        float4 v0 = *(const float4*)&Arow[ab];
        float4 v1 = *(const float4*)&Arow[ab + 4];
        aL[0]=v0.x; aL[1]=v0.y; aL[2]=v0.z; aL[3]=v0.w;
        aL[4]=v1.x; aL[5]=v1.y; aL[6]=v1.z; aL[7]=v1.w;
        const float* Bp = &B[(size_t)bk * N + c0 + bn];
        float4 w0 = *(const float4*)Bp;
        float4 w1 = *(const float4*)(Bp + 4);
        bL[0]=w0.x; bL[1]=w0.y; bL[2]=w0.z; bL[3]=w0.w;
        bL[4]=w1.x; bL[5]=w1.y; bL[6]=w1.z; bL[7]=w1.w;
        #pragma unroll
        for (int i = 0; i < 8; i++) {
            uint ah = f2tf32(aL[i]);
            uint bh = f2tf32(bL[i]);
            As2[(akq + i) * AST2 + am] =
                make_uint2(ah, f2tf32(aL[i] - __uint_as_float(ah)));
            Bs2[bk * AST2 + bn + i] =
                make_uint2(bh, f2tf32(bL[i] - __uint_as_float(bh)));
        }
    }
    __syncthreads();

    int buf = 0;
    for (int k0 = 0; k0 < K; k0 += 16) {
        bool more = (k0 + 16) < K;
        if (more) {
            int fk = k0 + 16 + akq;
            int ab = ((fk >> 8) << 14) + (fk & 255);
            float4 v0 = *(const float4*)&Arow[ab];
            float4 v1 = *(const float4*)&Arow[ab + 4];
            aL[0]=v0.x; aL[1]=v0.y; aL[2]=v0.z; aL[3]=v0.w;
            aL[4]=v1.x; aL[5]=v1.y; aL[6]=v1.z; aL[7]=v1.w;
            const float* Bp = &B[(size_t)(k0 + 16 + bk) * N + c0 + bn];
            float4 w0 = *(const float4*)Bp;
            float4 w1 = *(const float4*)(Bp + 4);
            bL[0]=w0.x; bL[1]=w0.y; bL[2]=w0.z; bL[3]=w0.w;
            bL[4]=w1.x; bL[5]=w1.y; bL[6]=w1.z; bL[7]=w1.w;
        }
        const uint2* as2 = As2 + buf * GT2;
        const uint2* bs2 = Bs2 + buf * GT2;
        #pragma unroll
        for (int kt = 0; kt < 2; kt++) {
            int kb = kt * 8;
            uint afH[4][4], afL[4][4], bfH[4][2], bfL[4][2];
            #pragma unroll
            for (int mt = 0; mt < 4; mt++) {
                int m = wm * 64 + mt * 16 + lg;
                int i0 = (kb + lk) * AST2 + m, i1 = (kb + lk + 4) * AST2 + m;
                uint2 v0 = as2[i0],     v1 = as2[i0 + 8];
                uint2 v2 = as2[i1],     v3 = as2[i1 + 8];
                afH[mt][0] = v0.x; afL[mt][0] = v0.y;
                afH[mt][1] = v1.x; afL[mt][1] = v1.y;
                afH[mt][2] = v2.x; afL[mt][2] = v2.y;
                afH[mt][3] = v3.x; afL[mt][3] = v3.y;
            }
            #pragma unroll
            for (int nt = 0; nt < 4; nt++) {
                int n = wn * 32 + nt * 8 + lg;
                uint2 w0 = bs2[(kb + lk) * AST2 + n];
                uint2 w1 = bs2[(kb + lk + 4) * AST2 + n];
                bfH[nt][0] = w0.x; bfL[nt][0] = w0.y;
                bfH[nt][1] = w1.x; bfL[nt][1] = w1.y;
            }
            #pragma unroll
            for (int mt = 0; mt < 4; mt++)
                #pragma unroll
                for (int nt = 0; nt < 4; nt++) {
                    asm("mma.sync.aligned.m16n8k8.row.col.f32.tf32.tf32.f32 "
                        "{%0,%1,%2,%3}, {%4,%5,%6,%7}, {%8,%9}, {%0,%1,%2,%3};"
                        : "+f"(c[mt][nt][0]), "+f"(c[mt][nt][1]),
                          "+f"(c[mt][nt][2]), "+f"(c[mt][nt][3])
                        : "r"(afL[mt][0]), "r"(afL[mt][1]),
                          "r"(afL[mt][2]), "r"(afL[mt][3]),
                          "r"(bfH[nt][0]), "r"(bfH[nt][1]));
                    asm("mma.sync.aligned.m16n8k8.row.col.f32.tf32.tf32.f32 "
                        "{%0,%1,%2,%3}, {%4,%5,%6,%7}, {%8,%9}, {%0,%1,%2,%3};"
                        : "+f"(c[mt][nt][0]), "+f"(c[mt][nt][1]),
                          "+f"(c[mt][nt][2]), "+f"(c[mt][nt][3])
                        : "r"(afH[mt][0]), "r"(afH[mt][1]),
                          "r"(afH[mt][2]), "r"(afH[mt][3]),
                          "r"(bfL[nt][0]), "r"(bfL[nt][1]));
                    asm("mma.sync.aligned.m16n8k8.row.col.f32.tf32.tf32.f32 "
                        "{%0,%1,%2,%3}, {%4,%5,%6,%7}, {%8,%9}, {%0,%1,%2,%3};"
                        : "+f"(c[mt][nt][0]), "+f"(c[mt][nt][1]),
                          "+f"(c[mt][nt][2]), "+f"(c[mt][nt][3])
                        : "r"(afH[mt][0]), "r"(afH[mt][1]),
                          "r"(afH[mt][2]), "r"(afH[mt][3]),
                          "r"(bfH[nt][0]), "r"(bfH[nt][1]));
                }
        }
        if (more) {
            uint2* aT = As2 + (buf ^ 1) * GT2;
            uint2* bT = Bs2 + (buf ^ 1) * GT2;
            #pragma unroll
            for (int i = 0; i < 8; i++) {
                uint ah = f2tf32(aL[i]);
                uint bh = f2tf32(bL[i]);
                aT[(akq + i) * AST2 + am] =
                    make_uint2(ah, f2tf32(aL[i] - __uint_as_float(ah)));
                bT[bk * AST2 + bn + i] =
                    make_uint2(bh, f2tf32(bL[i] - __uint_as_float(bh)));
            }
        }
        __syncthreads();
        buf ^= 1;
    }

    // epilogue: c0,c1 at (row lg, cols 2*lk, 2*lk+1); c2,c3 at row lg+8
    #pragma unroll
    for (int mt = 0; mt < 4; mt++) {
        #pragma unroll
        for (int nt = 0; nt < 4; nt++) {
            int row0 = r0 + wm * 64 + mt * 16 + lg;
            int col  = c0 + wn * 32 + nt * 8 + lk * 2;
            float v0 = c[mt][nt][0], v1 = c[mt][nt][1];
            float v2 = c[mt][nt][2], v3 = c[mt][nt][3];
            if (bias) {
                float bb0 = bias[col], bb1 = bias[col + 1];
                v0 += bb0; v1 += bb1; v2 += bb0; v3 += bb1;
            }
            if (C) {
                *(float2*)&C[(size_t)row0 * N + col] = make_float2(v0, v1);
                *(float2*)&C[(size_t)(row0 + 8) * N + col] = make_float2(v2, v3);
            }
            if (domax) {
                int ba = row0 & 63, bb = (row0 + 8) & 63;
                atomicMax(&g_enc[ba * 256 + col], enc_f(v0));
                atomicMax(&g_enc[ba * 256 + col + 1], enc_f(v1));
                atomicMax(&g_enc[bb * 256 + col], enc_f(v2));
                atomicMax(&g_enc[bb * 256 + col + 1], enc_f(v3));
            }
        }
    }
}

// ---------------- row LayerNorm over 768 cols, in place on g_s1 ------------
__global__ void ln_kernel(const float* __restrict__ gam,
                          const float* __restrict__ bet) {
    int row = blockIdx.x;
    float* p = g_s1 + (size_t)row * N3;
    int tid = threadIdx.x;
    float v0 = p[tid], v1 = p[tid + 256], v2 = p[tid + 512];
    float s = v0 + v1 + v2;
    float q = v0 * v0 + v1 * v1 + v2 * v2;
    __shared__ float rs[8], rq[8];
    __shared__ float tot[2];
    int lane = tid & 31, w = tid >> 5;
    #pragma unroll
    for (int o = 16; o; o >>= 1) {
        s += __shfl_down_sync(0xffffffffu, s, o);
        q += __shfl_down_sync(0xffffffffu, q, o);
    }
    if (!lane) { rs[w] = s; rq[w] = q; }
    __syncthreads();
    if (tid == 0) {
        float S = 0, Q = 0;
        for (int i = 0; i < 8; i++) { S += rs[i]; Q += rq[i]; }
        tot[0] = S; tot[1] = Q;
    }
    __syncthreads();
    float mean = tot[0] * (1.0f / 768.0f);
    float var = fmaxf(tot[1] * (1.0f / 768.0f) - mean * mean, 0.0f);
    float inv = 1.0f / (sqrtf(var + LN_EPS) + LN_EPS);
    p[tid]       = gam[tid]       * ((v0 - mean) * inv) + bet[tid];
    p[tid + 256] = gam[tid + 256] * ((v1 - mean) * inv) + bet[tid + 256];
    p[tid + 512] = gam[tid + 512] * ((v2 - mean) * inv) + bet[tid + 512];
}

// =============== recurrence: 32 clusters x 4 CTAs, U in REGISTERS ==========
// (R6-proven variant: 3x barrier.cluster per step; no mbarriers.)
// cluster c handles batch rows 2c, 2c+1 (packed in f32x2 lanes).
// Phase A: thread (colA = tid&127, khalf = tid>>7) owns U[:,gA] k-half.
// Phase B: thread (uB = tid&63, kq = tid>>6) owns U[:,512+gB] k-quarter.
// Phase C computed redundantly by ALL CTAs (z and sB broadcast) -> no h sync.
__global__ void __launch_bounds__(256, 1) __cluster_dims__(4, 1, 1)
rec_kernel(const int* __restrict__ x, const float* __restrict__ Umat,
           const float* __restrict__ s1, const float* __restrict__ gammas,
           const float* __restrict__ betas, float* __restrict__ out) {
    __shared__ __align__(16) float2 h2[256];    // h, local authoritative copy
    __shared__ __align__(16) float2 rh2[256];   // r*h (cluster-broadcast)
    __shared__ __align__(16) float2 z2g[256];   // z gates (cluster-broadcast)
    __shared__ __align__(16) float2 sBg[256];   // hc presums (cluster-broadcast)
    __shared__ __align__(16) float2 cbuf[192];  // intra-CTA partial exchange
    __shared__ float2 wsl[8];                   // warp reduction slots
    __shared__ float2 pA[8];                    // LN-A partials per rank (S,Q)
    __shared__ float2 pB[8];                    // LN-B partials per rank (S,Q)

    int tid  = threadIdx.x;
    uint rank = ctarank();
    int cid  = blockIdx.x >> 2;
    int b0   = cid * 2, b1 = b0 + 1;
    int lane = tid & 31, wid = tid >> 5;

    int colA  = tid & 127;
    int khalf = tid >> 7;
    int gA = (colA < 64) ? ((int)rank * 64 + colA)
                         : (256 + (int)rank * 64 + (colA - 64));
    float g1a = gammas[N3 + gA], be1a = betas[N3 + gA];
    int uC = tid;                                 // phase-C unit (0..255)
    float g1c = gammas[N3 + 512 + uC], be1c = betas[N3 + 512 + uC];
    int uB = tid & 63, kq = tid >> 6;
    int gB = (int)rank * 64 + uB;

    // ---- one-time: U slices into registers ----
    float UA[128];
    #pragma unroll
    for (int k = 0; k < 128; k++)
        UA[k] = Umat[(size_t)(khalf * 128 + k) * N3 + gA];
    float UB[64];
    #pragma unroll
    for (int j = 0; j < 64; j++)
        UB[j] = Umat[(size_t)(kq * 64 + j) * N3 + 512 + gB];

    h2[tid] = make_float2(0.0f, 0.0f);
    __syncthreads();
    CLUSTER_SYNC();

    for (int t = 0; t < TT; t++) {
        // prefetch s1 / masks (consumed late)
        const float* s1r0 = s1 + ((size_t)t * 64 + b0) * N3;
        const float* s1r1 = s1r0 + N3;
        float s1a0 = 0.0f, s1a1 = 0.0f;
        if (tid < 128) { s1a0 = s1r0[gA]; s1a1 = s1r1[gA]; }
        float s1c0 = s1r0[512 + uC], s1c1 = s1r1[512 + uC];
        int m0 = x[(size_t)b0 * TT + t], m1 = x[(size_t)b1 * TT + t];

        // ---- phase A: h @ U[:, gA] over k-half (U in regs, h broadcast) --
        const ull* hp = (const ull*)h2 + khalf * 128;
        ull a0 = 0, a1 = 0, a2 = 0, a3 = 0;
        #pragma unroll
        for (int k = 0; k < 128; k += 4) {
            ulonglong2 ha = *(const ulonglong2*)(hp + k);
            ulonglong2 hb = *(const ulonglong2*)(hp + k + 2);
            FMA2(a0, ha.x, UA[k]);     FMA2(a1, ha.y, UA[k + 1]);
            FMA2(a2, hb.x, UA[k + 2]); FMA2(a3, hb.y, UA[k + 3]);
        }
        float2 f0 = ull2f2(a0), f1 = ull2f2(a1);
        float2 f2v = ull2f2(a2), f3 = ull2f2(a3);
        float2 accA = make_float2((f0.x + f1.x) + (f2v.x + f3.x),
                                  (f0.y + f1.y) + (f2v.y + f3.y));
        if (tid >= 128) cbuf[tid - 128] = accA;
        __syncthreads();

        float2 sval = make_float2(0.0f, 0.0f);
        if (tid < 128) {
            float2 oth = cbuf[tid];
            sval.x = accA.x + oth.x; sval.y = accA.y + oth.y;
            float p0 = sval.x, p1 = sval.y;
            float q0 = p0 * p0, q1 = p1 * p1;
            #pragma unroll
            for (int o = 16; o; o >>= 1) {
                p0 += __shfl_down_sync(0xffffffffu, p0, o);
                p1 += __shfl_down_sync(0xffffffffu, p1, o);
                q0 += __shfl_down_sync(0xffffffffu, q0, o);
                q1 += __shfl_down_sync(0xffffffffu, q1, o);
            }
            if (!lane) { wsl[wid] = make_float2(p0, p1);
                         wsl[4 + wid] = make_float2(q0, q1); }
        }
        __syncthreads();
        if (tid == 0) {
            float2 S = make_float2(0, 0), Q = make_float2(0, 0);
            #pragma unroll
            for (int w = 0; w < 4; w++) {
                S.x += wsl[w].x; S.y += wsl[w].y;
                Q.x += wsl[4 + w].x; Q.y += wsl[4 + w].y;
            }
            #pragma unroll
            for (uint r = 0; r < 4; r++) {
                st_cl_b64(&pA[rank], r, f22ull(S));
                st_cl_b64(&pA[4 + rank], r, f22ull(Q));
            }
        }
        CLUSTER_SYNC();   // S1: LN-A partials visible everywhere

        // ---- gate: z broadcast, rh broadcast ----
        if (tid < 128) {
            float2 S = make_float2(0, 0), Q = make_float2(0, 0);
            #pragma unroll
            for (int r = 0; r < 4; r++) {
                S.x += pA[r].x; S.y += pA[r].y;
                Q.x += pA[4 + r].x; Q.y += pA[4 + r].y;
            }
            float mean0 = S.x * (1.0f / 512.0f), mean1 = S.y * (1.0f / 512.0f);
            float var0 = fmaxf(Q.x * (1.0f / 512.0f) - mean0 * mean0, 0.0f);
            float var1 = fmaxf(Q.y * (1.0f / 512.0f) - mean1 * mean1, 0.0f);
            float inv0 = 1.0f / (sqrtf(var0 + LN_EPS) + LN_EPS);
            float inv1 = 1.0f / (sqrtf(var1 + LN_EPS) + LN_EPS);
            float sv0 = hsig(s1a0 + g1a * ((sval.x - mean0) * inv0) + be1a);
            float sv1 = hsig(s1a1 + g1a * ((sval.y - mean1) * inv1) + be1a);
            if (colA < 64) {
                int gz = (int)rank * 64 + colA;
                ull pv = f22ull(make_float2(sv0, sv1));
                #pragma unroll
                for (uint r = 0; r < 4; r++) st_cl_b64(&z2g[gz], r, pv);
            } else {
                int uu = (int)rank * 64 + colA - 64;
                float2 h = h2[uu];
                ull pv = f22ull(make_float2(sv0 * h.x, sv1 * h.y));
                #pragma unroll
                for (uint r = 0; r < 4; r++) st_cl_b64(&rh2[uu], r, pv);
            }
        }
        CLUSTER_SYNC();   // S2: rh + z visible everywhere

        // ---- phase B: (r*h) @ U[:, 512+gB] over k-quarter ----
        const ull* rp = (const ull*)rh2 + kq * 64;
        ull b0a = 0, b1a = 0;
        #pragma unroll
        for (int j = 0; j < 64; j += 4) {
            ulonglong2 ra = *(const ulonglong2*)(rp + j);
            ulonglong2 rb = *(const ulonglong2*)(rp + j + 2);
            FMA2(b0a, ra.x, UB[j]);     FMA2(b1a, ra.y, UB[j + 1]);
            FMA2(b0a, rb.x, UB[j + 2]); FMA2(b1a, rb.y, UB[j + 3]);
        }
        float2 g0 = ull2f2(b0a), g1 = ull2f2(b1a);
        float2 accB = make_float2(g0.x + g1.x, g0.y + g1.y);
        if (tid >= 64) cbuf[tid - 64] = accB;
        __syncthreads();

        if (tid < 64) {
            float2 o1 = cbuf[tid], o2 = cbuf[64 + tid], o3 = cbuf[128 + tid];
            float2 sB = make_float2(accB.x + o1.x + o2.x + o3.x,
                                    accB.y + o1.y + o2.y + o3.y);
            ull pv = f22ull(sB);
            #pragma unroll
            for (uint r = 0; r < 4; r++) st_cl_b64(&sBg[gB], r, pv);
            float p0 = sB.x, p1 = sB.y, q0 = p0 * p0, q1 = p1 * p1;
            #pragma unroll
            for (int o = 16; o; o >>= 1) {
                p0 += __shfl_down_sync(0xffffffffu, p0, o);
                p1 += __shfl_down_sync(0xffffffffu, p1, o);
                q0 += __shfl_down_sync(0xffffffffu, q0, o);
                q1 += __shfl_down_sync(0xffffffffu, q1, o);
            }
            if (!lane) { wsl[wid] = make_float2(p0, p1);
                         wsl[4 + wid] = make_float2(q0, q1); }
        }
        __syncthreads();
        if (tid == 0) {
            float2 S = make_float2(wsl[0].x + wsl[1].x, wsl[0].y + wsl[1].y);
            float2 Q = make_float2(wsl[4].x + wsl[5].x, wsl[4].y + wsl[5].y);
            #pragma unroll
            for (uint r = 0; r < 4; r++) {
                st_cl_b64(&pB[rank], r, f22ull(S));
                st_cl_b64(&pB[4 + rank], r, f22ull(Q));
            }
        }
        CLUSTER_SYNC();   // S3: sB + LN-B partials visible everywhere

        // ---- phase C: computed redundantly by ALL CTAs; h stays local ----
        {
            float2 S = make_float2(0, 0), Q = make_float2(0, 0);
            #pragma unroll
            for (int r = 0; r < 4; r++) {
                S.x += pB[r].x; S.y += pB[r].y;
                Q.x += pB[4 + r].x; Q.y += pB[4 + r].y;
            }
            float mean0 = S.x * (1.0f / 256.0f), mean1 = S.y * (1.0f / 256.0f);
            float var0 = fmaxf(Q.x * (1.0f / 256.0f) - mean0 * mean0, 0.0f);
            float var1 = fmaxf(Q.y * (1.0f / 256.0f) - mean1 * mean1, 0.0f);
            float inv0 = 1.0f / (sqrtf(var0 + LN_EPS) + LN_EPS);
            float inv1 = 1.0f / (sqrtf(var1 + LN_EPS) + LN_EPS);
            float2 sB = sBg[uC];
            float hc0 = tanhf(s1c0 + g1c * ((sB.x - mean0) * inv0) + be1c);
            float hc1 = tanhf(s1c1 + g1c * ((sB.y - mean1) * inv1) + be1c);
            float2 z = z2g[uC];
            float2 h = h2[uC];
            float hn0 = z.x * h.x + (1.0f - z.x) * hc0;
            float hn1 = z.y * h.y + (1.0f - z.y) * hc1;
            h2[uC] = make_float2(m0 ? hn0 : h.x, m1 ? hn1 : h.y);
        }
        __syncthreads();   // h2 complete before next phase A (CTA-local)
    }

    if (rank == 0) {
        float2 h = h2[uC];
        out[(size_t)b0 * 512 + uC] = h.x;
        out[(size_t)b1 * 512 + uC] = h.y;
    }
}

// ---------------- launch ---------------------------------------------------
extern "C" void kernel_launch(void* const* d_in, const int* in_sizes, int n_in,
                              void* d_out, int out_size) {
    const int* x           = (const int*)d_in[0];   // token ids (int32)
    const float* emb       = (const float*)d_in[2];
    const float* W         = (const float*)d_in[3];
    const float* Umat      = (const float*)d_in[4];
    const float* bias      = (const float*)d_in[5];
    const float* gammas    = (const float*)d_in[6];
    const float* betas     = (const float*)d_in[7];
    const float* kern      = (const float*)d_in[8];
    float* out             = (float*)d_out;

    float *xe, *s1p;
    cudaGetSymbolAddress((void**)&xe, g_xemb);
    cudaGetSymbolAddress((void**)&s1p, g_s1);

    const int gsm = 4 * GT2 * (int)sizeof(uint2);   // 67584 B
    cudaFuncSetAttribute(gemm_tc, cudaFuncAttributeMaxDynamicSharedMemorySize,
                         gsm);

    // 1) embedding gather
    embed_kernel<<<TT * BB, 256>>>(x, emb);
    // 2) s1 = x_emb @ W + b  (M=32768, N=768, K=256), then LN in place
    gemm_tc<<<dim3(N3 / 128, TT * BB / 128), 256, gsm>>>(xe, W, bias, s1p,
                                                         N3, NU, 0);
    ln_kernel<<<TT * BB, 256>>>(gammas, betas);
    // 3) conv as ONE K=768 GEMM (M = 510*64 = 32640 = 255*128) with fused max
    encinit_kernel<<<BB, 256>>>();
    gemm_tc<<<dim3(NU / 128, (510 * BB) / 128), 256, gsm>>>(xe, kern, nullptr,
                                                            nullptr, NU,
                                                            3 * NU, 1);
    decode_kernel<<<BB, 256>>>(out);
    // 4) recurrence: cluster-parallel, U register-resident (R6-proven sync)
    rec_kernel<<<128, 256>>>(x, Umat, s1p, gammas, betas, out);
}

// round 12
// speedup vs baseline: 1.6120x; 1.2805x over previous
#include <cuda_runtime.h>
#include <cuda_bf16.h>
#include <math.h>

// Problem constants (fixed shapes)
#define BB 64      // batch
#define TT 512     // time / bucket_size
#define NU 256     // units
#define N3 768     // 3*units
#define LN_EPS 1e-5f

typedef unsigned long long ull;
typedef unsigned int uint;

// ---------------- scratch (static device arrays; no runtime allocation) ----
__device__ float g_xemb[TT * BB * NU];   // [t][b][c]   33.5 MB
__device__ float g_s1[TT * BB * N3];     // [t][b][768] 100 MB (LN'd in place)
__device__ uint  g_enc[BB * NU];         // encoded running max for conv

// ---------------- small helpers -------------------------------------------
__device__ __forceinline__ uint enc_f(float v) {
    uint u = __float_as_uint(v);
    return ((int)u < 0) ? ~u : (u | 0x80000000u);
}
__device__ __forceinline__ float dec_f(uint e) {
    uint u = (e & 0x80000000u) ? (e ^ 0x80000000u) : ~e;
    return __uint_as_float(u);
}
__device__ __forceinline__ float hsig(float v) {
    return fminf(fmaxf(0.2f * v + 0.5f, 0.0f), 1.0f);
}
__device__ __forceinline__ float2 ull2f2(ull v) {
    float2 r;
    asm("mov.b64 {%0, %1}, %2;" : "=f"(r.x), "=f"(r.y) : "l"(v));
    return r;
}
__device__ __forceinline__ ull f22ull(float2 v) {
    ull r;
    asm("mov.b64 %0, {%1, %2};" : "=l"(r) : "f"(v.x), "f"(v.y));
    return r;
}
// packed fma: acc.{lo,hi} += hk.{lo,hi} * u
#define FMA2(acc, hk, uval) do {                                          \
    ull _pu;                                                              \
    asm("mov.b64 %0, {%1, %1};" : "=l"(_pu) : "f"(uval));                 \
    asm("fma.rn.f32x2 %0, %1, %2, %0;" : "+l"(acc) : "l"(hk), "l"(_pu));  \
} while (0)

__device__ __forceinline__ uint ctarank() {
    uint r; asm("mov.u32 %0, %%cluster_ctarank;" : "=r"(r)); return r;
}
__device__ __forceinline__ void st_cl_b64(void* laddr, uint r, ull v) {
    uint la = (uint)__cvta_generic_to_shared(laddr);
    asm volatile(
        "{ .reg .b32 ra; mapa.shared::cluster.u32 ra, %0, %1; "
        "st.shared::cluster.b64 [ra], %2; }"
        :: "r"(la), "r"(r), "l"(v) : "memory");
}
#define CLUSTER_SYNC() do {                                        \
    asm volatile("barrier.cluster.arrive.aligned;" ::: "memory");  \
    asm volatile("barrier.cluster.wait.aligned;" ::: "memory");    \
} while (0)

// bf16x3 split: pack two consecutive-k fp32 values into {hiPair, midPair}.
// low 16 bits = first (even-k) element, matching m16n8k16 fragment order.
__device__ __forceinline__ uint2 bf16x3_pack(float va, float vb) {
    __nv_bfloat16 ha = __float2bfloat16(va);
    __nv_bfloat16 hb = __float2bfloat16(vb);
    float ra = va - __bfloat162float(ha);
    float rb = vb - __bfloat162float(hb);
    __nv_bfloat16 ma = __float2bfloat16(ra);
    __nv_bfloat16 mb = __float2bfloat16(rb);
    uint hi  = ((uint)__bfloat16_as_ushort(hb) << 16) |
               (uint)__bfloat16_as_ushort(ha);
    uint mid = ((uint)__bfloat16_as_ushort(mb) << 16) |
               (uint)__bfloat16_as_ushort(ma);
    return make_uint2(hi, mid);
}

#define MMA_BF16(cc, a0, a1, a2, a3, b0, b1)                              \
    asm("mma.sync.aligned.m16n8k16.row.col.f32.bf16.bf16.f32 "            \
        "{%0,%1,%2,%3}, {%4,%5,%6,%7}, {%8,%9}, {%0,%1,%2,%3};"           \
        : "+f"(cc[0]), "+f"(cc[1]), "+f"(cc[2]), "+f"(cc[3])              \
        : "r"(a0), "r"(a1), "r"(a2), "r"(a3), "r"(b0), "r"(b1))

// ---------------- embedding gather (+ g_enc init fused) --------------------
__global__ void embed_kernel(const int* __restrict__ x,
                             const float* __restrict__ emb) {
    int idx = blockIdx.x * 256 + threadIdx.x;
    int c = idx & 255;
    int b = (idx >> 8) & 63;
    int t = idx >> 14;
    int row = x[(size_t)b * TT + t];
    g_xemb[idx] = emb[(size_t)row * NU + c];
    if (blockIdx.x < 64)
        g_enc[blockIdx.x * 256 + threadIdx.x] = enc_f(-INFINITY);
}

__global__ void decode_kernel(float* __restrict__ out) {
    int f = threadIdx.x;           // 256
    int b = blockIdx.x;            // 64
    out[(size_t)b * 512 + 256 + f] = dec_f(g_enc[b * 256 + f]);
}

// ---------------- 128x128 bf16x3 tensor-core GEMM --------------------------
// C(MxN) = A(MxK) * B(KxN) at ~1e-5 accuracy: fp32 -> bf16 hi + bf16 mid,
// acc += AhBh + AhBm + AmBh (dropped terms ~2^-18). m16n8k16: K=16/MMA, so
// 3 MMAs per BK=16 chunk (half the MMA count of 3xTF32 at k8).
// hi/mid pair-packed in smem as uint2 per (kpair, m): one LDS.64 = both.
// A uses g_xemb segment addressing:
//   A[row,k] = A[row*256 + (k>>8)*16384 + (k&255)]  (row-major when K=256;
//   realizes the width-3 conv as one GEMM when K=768).
// BK=16 -> 8 kpair-rows, 256 threads = 8 warps (2 m x 4 n), warp 64x32.
// smem stride 132 uint2 (8-bank row shift -> conflict-free frags).
#define AST2 132
#define GTB (8 * AST2)      // uint2 per tile (8 kpair rows x 132)
__global__ void __launch_bounds__(256)
gemm_tc(const float* __restrict__ A, const float* __restrict__ B,
        const float* __restrict__ bias, float* __restrict__ C,
        int N, int K, int domax) {
    extern __shared__ uint2 dsm2[];
    uint2* As2 = dsm2;               // [2][GTB]
    uint2* Bs2 = dsm2 + 2 * GTB;     // [2][GTB]

    int tid = threadIdx.x;
    int lane = tid & 31, warp = tid >> 5;
    int wm = warp >> 2, wn = warp & 3;           // warp grid 2x4
    int lk = lane & 3, lg = lane >> 2;
    int r0 = blockIdx.y * 128, c0 = blockIdx.x * 128;

    // staging roles
    int am = tid >> 1, akq = (tid & 1) * 8;      // A: row am, 8 k's (4 pairs)
    int aRow0 = (tid & 1) * 4;                   // kpair row base for A stores
    int bkp = tid >> 5, bn4 = (tid & 31) * 4;    // B: kpair row bkp, 4 n's

    float c[4][4][4];
    #pragma unroll
    for (int i = 0; i < 4; i++)
        #pragma unroll
        for (int j = 0; j < 4; j++)
            #pragma unroll
            for (int q = 0; q < 4; q++) c[i][j][q] = 0.0f;

    const float* Arow = A + (size_t)(r0 + am) * 256;

    float aL[8], bL0[4], bL1[4];
    {   // prefetch tile 0
        int fk = akq;
        int ab = ((fk >> 8) << 14) + (fk & 255);
        float4 v0 = *(const float4*)&Arow[ab];
        float4 v1 = *(const float4*)&Arow[ab + 4];
        aL[0]=v0.x; aL[1]=v0.y; aL[2]=v0.z; aL[3]=v0.w;
        aL[4]=v1.x; aL[5]=v1.y; aL[6]=v1.z; aL[7]=v1.w;
        const float* Bp0 = &B[(size_t)(2 * bkp) * N + c0 + bn4];
        const float* Bp1 = Bp0 + N;
        float4 w0 = *(const float4*)Bp0;
        float4 w1 = *(const float4*)Bp1;
        bL0[0]=w0.x; bL0[1]=w0.y; bL0[2]=w0.z; bL0[3]=w0.w;
        bL1[0]=w1.x; bL1[1]=w1.y; bL1[2]=w1.z; bL1[3]=w1.w;
        #pragma unroll
        for (int j = 0; j < 4; j++) {
            As2[(aRow0 + j) * AST2 + am] = bf16x3_pack(aL[2*j], aL[2*j+1]);
            Bs2[bkp * AST2 + bn4 + j]    = bf16x3_pack(bL0[j], bL1[j]);
        }
    }
    __syncthreads();

    int buf = 0;
    for (int k0 = 0; k0 < K; k0 += 16) {
        bool more = (k0 + 16) < K;
        if (more) {
            int fk = k0 + 16 + akq;
            int ab = ((fk >> 8) << 14) + (fk & 255);
            float4 v0 = *(const float4*)&Arow[ab];
            float4 v1 = *(const float4*)&Arow[ab + 4];
            aL[0]=v0.x; aL[1]=v0.y; aL[2]=v0.z; aL[3]=v0.w;
            aL[4]=v1.x; aL[5]=v1.y; aL[6]=v1.z; aL[7]=v1.w;
            const float* Bp0 = &B[(size_t)(k0 + 16 + 2 * bkp) * N + c0 + bn4];
            const float* Bp1 = Bp0 + N;
            float4 w0 = *(const float4*)Bp0;
            float4 w1 = *(const float4*)Bp1;
            bL0[0]=w0.x; bL0[1]=w0.y; bL0[2]=w0.z; bL0[3]=w0.w;
            bL1[0]=w1.x; bL1[1]=w1.y; bL1[2]=w1.z; bL1[3]=w1.w;
        }
        const uint2* as2 = As2 + buf * GTB;
        const uint2* bs2 = Bs2 + buf * GTB;
        {
            uint afH[4][4], afM[4][4], bfH[4][2], bfM[4][2];
            #pragma unroll
            for (int mt = 0; mt < 4; mt++) {
                int m = wm * 64 + mt * 16 + lg;
                int i0 = lk * AST2 + m, i1 = (lk + 4) * AST2 + m;
                uint2 v0 = as2[i0], v1 = as2[i0 + 8];
                uint2 v2 = as2[i1], v3 = as2[i1 + 8];
                afH[mt][0] = v0.x; afM[mt][0] = v0.y;
                afH[mt][1] = v1.x; afM[mt][1] = v1.y;
                afH[mt][2] = v2.x; afM[mt][2] = v2.y;
                afH[mt][3] = v3.x; afM[mt][3] = v3.y;
            }
            #pragma unroll
            for (int nt = 0; nt < 4; nt++) {
                int n = wn * 32 + nt * 8 + lg;
                uint2 w0 = bs2[lk * AST2 + n];
                uint2 w1 = bs2[(lk + 4) * AST2 + n];
                bfH[nt][0] = w0.x; bfM[nt][0] = w0.y;
                bfH[nt][1] = w1.x; bfM[nt][1] = w1.y;
            }
            #pragma unroll
            for (int mt = 0; mt < 4; mt++)
                #pragma unroll
                for (int nt = 0; nt < 4; nt++) {
                    MMA_BF16(c[mt][nt], afM[mt][0], afM[mt][1], afM[mt][2],
                             afM[mt][3], bfH[nt][0], bfH[nt][1]);
                    MMA_BF16(c[mt][nt], afH[mt][0], afH[mt][1], afH[mt][2],
                             afH[mt][3], bfM[nt][0], bfM[nt][1]);
                    MMA_BF16(c[mt][nt], afH[mt][0], afH[mt][1], afH[mt][2],
                             afH[mt][3], bfH[nt][0], bfH[nt][1]);
                }
        }
        if (more) {
            uint2* aT = As2 + (buf ^ 1) * GTB;
            uint2* bT = Bs2 + (buf ^ 1) * GTB;
            #pragma unroll
            for (int j = 0; j < 4; j++) {
                aT[(aRow0 + j) * AST2 + am] = bf16x3_pack(aL[2*j], aL[2*j+1]);
                bT[bkp * AST2 + bn4 + j]    = bf16x3_pack(bL0[j], bL1[j]);
            }
        }
        __syncthreads();
        buf ^= 1;
    }

    // epilogue: c0,c1 at (row lg, cols 2*lk, 2*lk+1); c2,c3 at row lg+8
    #pragma unroll
    for (int mt = 0; mt < 4; mt++) {
        #pragma unroll
        for (int nt = 0; nt < 4; nt++) {
            int row0 = r0 + wm * 64 + mt * 16 + lg;
            int col  = c0 + wn * 32 + nt * 8 + lk * 2;
            float v0 = c[mt][nt][0], v1 = c[mt][nt][1];
            float v2 = c[mt][nt][2], v3 = c[mt][nt][3];
            if (bias) {
                float bb0 = bias[col], bb1 = bias[col + 1];
                v0 += bb0; v1 += bb1; v2 += bb0; v3 += bb1;
            }
            if (C) {
                *(float2*)&C[(size_t)row0 * N + col] = make_float2(v0, v1);
                *(float2*)&C[(size_t)(row0 + 8) * N + col] = make_float2(v2, v3);
            }
            if (domax) {
                int ba = row0 & 63, bb = (row0 + 8) & 63;
                atomicMax(&g_enc[ba * 256 + col], enc_f(v0));
                atomicMax(&g_enc[ba * 256 + col + 1], enc_f(v1));
                atomicMax(&g_enc[bb * 256 + col], enc_f(v2));
                atomicMax(&g_enc[bb * 256 + col + 1], enc_f(v3));
            }
        }
    }
}

// ---------------- row LayerNorm over 768 cols, in place on g_s1 ------------
__global__ void ln_kernel(const float* __restrict__ gam,
                          const float* __restrict__ bet) {
    int row = blockIdx.x;
    float* p = g_s1 + (size_t)row * N3;
    int tid = threadIdx.x;
    float v0 = p[tid], v1 = p[tid + 256], v2 = p[tid + 512];
    float s = v0 + v1 + v2;
    float q = v0 * v0 + v1 * v1 + v2 * v2;
    __shared__ float rs[8], rq[8];
    __shared__ float tot[2];
    int lane = tid & 31, w = tid >> 5;
    #pragma unroll
    for (int o = 16; o; o >>= 1) {
        s += __shfl_down_sync(0xffffffffu, s, o);
        q += __shfl_down_sync(0xffffffffu, q, o);
    }
    if (!lane) { rs[w] = s; rq[w] = q; }
    __syncthreads();
    if (tid == 0) {
        float S = 0, Q = 0;
        for (int i = 0; i < 8; i++) { S += rs[i]; Q += rq[i]; }
        tot[0] = S; tot[1] = Q;
    }
    __syncthreads();
    float mean = tot[0] * (1.0f / 768.0f);
    float var = fmaxf(tot[1] * (1.0f / 768.0f) - mean * mean, 0.0f);
    float inv = 1.0f / (sqrtf(var + LN_EPS) + LN_EPS);
    p[tid]       = gam[tid]       * ((v0 - mean) * inv) + bet[tid];
    p[tid + 256] = gam[tid + 256] * ((v1 - mean) * inv) + bet[tid + 256];
    p[tid + 512] = gam[tid + 512] * ((v2 - mean) * inv) + bet[tid + 512];
}

// =============== recurrence: 32 clusters x 4 CTAs, U in REGISTERS ==========
// (R6/R10-proven variant: 3x barrier.cluster per step; no mbarriers.)
// cluster c handles batch rows 2c, 2c+1 (packed in f32x2 lanes).
// Phase A: thread (colA = tid&127, khalf = tid>>7) owns U[:,gA] k-half.
// Phase B: thread (uB = tid&63, kq = tid>>6) owns U[:,512+gB] k-quarter.
// Phase C computed redundantly by ALL CTAs (z and sB broadcast) -> no h sync.
__global__ void __launch_bounds__(256, 1) __cluster_dims__(4, 1, 1)
rec_kernel(const int* __restrict__ x, const float* __restrict__ Umat,
           const float* __restrict__ s1, const float* __restrict__ gammas,
           const float* __restrict__ betas, float* __restrict__ out) {
    __shared__ __align__(16) float2 h2[256];    // h, local authoritative copy
    __shared__ __align__(16) float2 rh2[256];   // r*h (cluster-broadcast)
    __shared__ __align__(16) float2 z2g[256];   // z gates (cluster-broadcast)
    __shared__ __align__(16) float2 sBg[256];   // hc presums (cluster-broadcast)
    __shared__ __align__(16) float2 cbuf[192];  // intra-CTA partial exchange
    __shared__ float2 wsl[8];                   // warp reduction slots
    __shared__ float2 pA[8];                    // LN-A partials per rank (S,Q)
    __shared__ float2 pB[8];                    // LN-B partials per rank (S,Q)

    int tid  = threadIdx.x;
    uint rank = ctarank();
    int cid  = blockIdx.x >> 2;
    int b0   = cid * 2, b1 = b0 + 1;
    int lane = tid & 31, wid = tid >> 5;

    int colA  = tid & 127;
    int khalf = tid >> 7;
    int gA = (colA < 64) ? ((int)rank * 64 + colA)
                         : (256 + (int)rank * 64 + (colA - 64));
    float g1a = gammas[N3 + gA], be1a = betas[N3 + gA];
    int uC = tid;                                 // phase-C unit (0..255)
    float g1c = gammas[N3 + 512 + uC], be1c = betas[N3 + 512 + uC];
    int uB = tid & 63, kq = tid >> 6;
    int gB = (int)rank * 64 + uB;

    // ---- one-time: U slices into registers ----
    float UA[128];
    #pragma unroll
    for (int k = 0; k < 128; k++)
        UA[k] = Umat[(size_t)(khalf * 128 + k) * N3 + gA];
    float UB[64];
    #pragma unroll
    for (int j = 0; j < 64; j++)
        UB[j] = Umat[(size_t)(kq * 64 + j) * N3 + 512 + gB];

    h2[tid] = make_float2(0.0f, 0.0f);
    __syncthreads();
    CLUSTER_SYNC();

    for (int t = 0; t < TT; t++) {
        // prefetch s1 / masks (consumed late)
        const float* s1r0 = s1 + ((size_t)t * 64 + b0) * N3;
        const float* s1r1 = s1r0 + N3;
        float s1a0 = 0.0f, s1a1 = 0.0f;
        if (tid < 128) { s1a0 = s1r0[gA]; s1a1 = s1r1[gA]; }
        float s1c0 = s1r0[512 + uC], s1c1 = s1r1[512 + uC];
        int m0 = x[(size_t)b0 * TT + t], m1 = x[(size_t)b1 * TT + t];

        // ---- phase A: h @ U[:, gA] over k-half (U in regs, h broadcast) --
        const ull* hp = (const ull*)h2 + khalf * 128;
        ull a0 = 0, a1 = 0, a2 = 0, a3 = 0;
        #pragma unroll
        for (int k = 0; k < 128; k += 4) {
            ulonglong2 ha = *(const ulonglong2*)(hp + k);
            ulonglong2 hb = *(const ulonglong2*)(hp + k + 2);
            FMA2(a0, ha.x, UA[k]);     FMA2(a1, ha.y, UA[k + 1]);
            FMA2(a2, hb.x, UA[k + 2]); FMA2(a3, hb.y, UA[k + 3]);
        }
        float2 f0 = ull2f2(a0), f1 = ull2f2(a1);
        float2 f2v = ull2f2(a2), f3 = ull2f2(a3);
        float2 accA = make_float2((f0.x + f1.x) + (f2v.x + f3.x),
                                  (f0.y + f1.y) + (f2v.y + f3.y));
        if (tid >= 128) cbuf[tid - 128] = accA;
        __syncthreads();

        float2 sval = make_float2(0.0f, 0.0f);
        if (tid < 128) {
            float2 oth = cbuf[tid];
            sval.x = accA.x + oth.x; sval.y = accA.y + oth.y;
            float p0 = sval.x, p1 = sval.y;
            float q0 = p0 * p0, q1 = p1 * p1;
            #pragma unroll
            for (int o = 16; o; o >>= 1) {
                p0 += __shfl_down_sync(0xffffffffu, p0, o);
                p1 += __shfl_down_sync(0xffffffffu, p1, o);
                q0 += __shfl_down_sync(0xffffffffu, q0, o);
                q1 += __shfl_down_sync(0xffffffffu, q1, o);
            }
            if (!lane) { wsl[wid] = make_float2(p0, p1);
                         wsl[4 + wid] = make_float2(q0, q1); }
        }
        __syncthreads();
        if (tid == 0) {
            float2 S = make_float2(0, 0), Q = make_float2(0, 0);
            #pragma unroll
            for (int w = 0; w < 4; w++) {
                S.x += wsl[w].x; S.y += wsl[w].y;
                Q.x += wsl[4 + w].x; Q.y += wsl[4 + w].y;
            }
            #pragma unroll
            for (uint r = 0; r < 4; r++) {
                st_cl_b64(&pA[rank], r, f22ull(S));
                st_cl_b64(&pA[4 + rank], r, f22ull(Q));
            }
        }
        CLUSTER_SYNC();   // S1: LN-A partials visible everywhere

        // ---- gate: z broadcast, rh broadcast ----
        if (tid < 128) {
            float2 S = make_float2(0, 0), Q = make_float2(0, 0);
            #pragma unroll
            for (int r = 0; r < 4; r++) {
                S.x += pA[r].x; S.y += pA[r].y;
                Q.x += pA[4 + r].x; Q.y += pA[4 + r].y;
            }
            float mean0 = S.x * (1.0f / 512.0f), mean1 = S.y * (1.0f / 512.0f);
            float var0 = fmaxf(Q.x * (1.0f / 512.0f) - mean0 * mean0, 0.0f);
            float var1 = fmaxf(Q.y * (1.0f / 512.0f) - mean1 * mean1, 0.0f);
            float inv0 = 1.0f / (sqrtf(var0 + LN_EPS) + LN_EPS);
            float inv1 = 1.0f / (sqrtf(var1 + LN_EPS) + LN_EPS);
            float sv0 = hsig(s1a0 + g1a * ((sval.x - mean0) * inv0) + be1a);
            float sv1 = hsig(s1a1 + g1a * ((sval.y - mean1) * inv1) + be1a);
            if (colA < 64) {
                int gz = (int)rank * 64 + colA;
                ull pv = f22ull(make_float2(sv0, sv1));
                #pragma unroll
                for (uint r = 0; r < 4; r++) st_cl_b64(&z2g[gz], r, pv);
            } else {
                int uu = (int)rank * 64 + colA - 64;
                float2 h = h2[uu];
                ull pv = f22ull(make_float2(sv0 * h.x, sv1 * h.y));
                #pragma unroll
                for (uint r = 0; r < 4; r++) st_cl_b64(&rh2[uu], r, pv);
            }
        }
        CLUSTER_SYNC();   // S2: rh + z visible everywhere

        // ---- phase B: (r*h) @ U[:, 512+gB] over k-quarter ----
        const ull* rp = (const ull*)rh2 + kq * 64;
        ull b0a = 0, b1a = 0;
        #pragma unroll
        for (int j = 0; j < 64; j += 4) {
            ulonglong2 ra = *(const ulonglong2*)(rp + j);
            ulonglong2 rb = *(const ulonglong2*)(rp + j + 2);
            FMA2(b0a, ra.x, UB[j]);     FMA2(b1a, ra.y, UB[j + 1]);
            FMA2(b0a, rb.x, UB[j + 2]); FMA2(b1a, rb.y, UB[j + 3]);
        }
        float2 g0 = ull2f2(b0a), g1 = ull2f2(b1a);
        float2 accB = make_float2(g0.x + g1.x, g0.y + g1.y);
        if (tid >= 64) cbuf[tid - 64] = accB;
        __syncthreads();

        if (tid < 64) {
            float2 o1 = cbuf[tid], o2 = cbuf[64 + tid], o3 = cbuf[128 + tid];
            float2 sB = make_float2(accB.x + o1.x + o2.x + o3.x,
                                    accB.y + o1.y + o2.y + o3.y);
            ull pv = f22ull(sB);
            #pragma unroll
            for (uint r = 0; r < 4; r++) st_cl_b64(&sBg[gB], r, pv);
            float p0 = sB.x, p1 = sB.y, q0 = p0 * p0, q1 = p1 * p1;
            #pragma unroll
            for (int o = 16; o; o >>= 1) {
                p0 += __shfl_down_sync(0xffffffffu, p0, o);
                p1 += __shfl_down_sync(0xffffffffu, p1, o);
                q0 += __shfl_down_sync(0xffffffffu, q0, o);
                q1 += __shfl_down_sync(0xffffffffu, q1, o);
            }
            if (!lane) { wsl[wid] = make_float2(p0, p1);
                         wsl[4 + wid] = make_float2(q0, q1); }
        }
        __syncthreads();
        if (tid == 0) {
            float2 S = make_float2(wsl[0].x + wsl[1].x, wsl[0].y + wsl[1].y);
            float2 Q = make_float2(wsl[4].x + wsl[5].x, wsl[4].y + wsl[5].y);
            #pragma unroll
            for (uint r = 0; r < 4; r++) {
                st_cl_b64(&pB[rank], r, f22ull(S));
                st_cl_b64(&pB[4 + rank], r, f22ull(Q));
            }
        }
        CLUSTER_SYNC();   // S3: sB + LN-B partials visible everywhere

        // ---- phase C: computed redundantly by ALL CTAs; h stays local ----
        {
            float2 S = make_float2(0, 0), Q = make_float2(0, 0);
            #pragma unroll
            for (int r = 0; r < 4; r++) {
                S.x += pB[r].x; S.y += pB[r].y;
                Q.x += pB[4 + r].x; Q.y += pB[4 + r].y;
            }
            float mean0 = S.x * (1.0f / 256.0f), mean1 = S.y * (1.0f / 256.0f);
            float var0 = fmaxf(Q.x * (1.0f / 256.0f) - mean0 * mean0, 0.0f);
            float var1 = fmaxf(Q.y * (1.0f / 256.0f) - mean1 * mean1, 0.0f);
            float inv0 = 1.0f / (sqrtf(var0 + LN_EPS) + LN_EPS);
            float inv1 = 1.0f / (sqrtf(var1 + LN_EPS) + LN_EPS);
            float2 sB = sBg[uC];
            float hc0 = tanhf(s1c0 + g1c * ((sB.x - mean0) * inv0) + be1c);
            float hc1 = tanhf(s1c1 + g1c * ((sB.y - mean1) * inv1) + be1c);
            float2 z = z2g[uC];
            float2 h = h2[uC];
            float hn0 = z.x * h.x + (1.0f - z.x) * hc0;
            float hn1 = z.y * h.y + (1.0f - z.y) * hc1;
            h2[uC] = make_float2(m0 ? hn0 : h.x, m1 ? hn1 : h.y);
        }
        __syncthreads();   // h2 complete before next phase A (CTA-local)
    }

    if (rank == 0) {
        float2 h = h2[uC];
        out[(size_t)b0 * 512 + uC] = h.x;
        out[(size_t)b1 * 512 + uC] = h.y;
    }
}

// ---------------- launch ---------------------------------------------------
extern "C" void kernel_launch(void* const* d_in, const int* in_sizes, int n_in,
                              void* d_out, int out_size) {
    const int* x           = (const int*)d_in[0];   // token ids (int32)
    const float* emb       = (const float*)d_in[2];
    const float* W         = (const float*)d_in[3];
    const float* Umat      = (const float*)d_in[4];
    const float* bias      = (const float*)d_in[5];
    const float* gammas    = (const float*)d_in[6];
    const float* betas     = (const float*)d_in[7];
    const float* kern      = (const float*)d_in[8];
    float* out             = (float*)d_out;

    float *xe, *s1p;
    cudaGetSymbolAddress((void**)&xe, g_xemb);
    cudaGetSymbolAddress((void**)&s1p, g_s1);

    const int gsm = 4 * GTB * (int)sizeof(uint2);   // 33792 B
    cudaFuncSetAttribute(gemm_tc, cudaFuncAttributeMaxDynamicSharedMemorySize,
                         gsm);

    // 1) embedding gather (+ g_enc init fused)
    embed_kernel<<<TT * BB, 256>>>(x, emb);
    // 2) s1 = x_emb @ W + b  (M=32768, N=768, K=256), then LN in place
    gemm_tc<<<dim3(N3 / 128, TT * BB / 128), 256, gsm>>>(xe, W, bias, s1p,
                                                         N3, NU, 0);
    ln_kernel<<<TT * BB, 256>>>(gammas, betas);
    // 3) conv as ONE K=768 GEMM (M = 510*64 = 32640 = 255*128) with fused max
    gemm_tc<<<dim3(NU / 128, (510 * BB) / 128), 256, gsm>>>(xe, kern, nullptr,
                                                            nullptr, NU,
                                                            3 * NU, 1);
    decode_kernel<<<BB, 256>>>(out);
    // 4) recurrence: cluster-parallel, U register-resident (proven sync)
    rec_kernel<<<128, 256>>>(x, Umat, s1p, gammas, betas, out);
}

// round 13
// speedup vs baseline: 1.7325x; 1.0747x over previous
#include <cuda_runtime.h>
#include <cuda_bf16.h>
#include <math.h>

// Problem constants (fixed shapes)
#define BB 64      // batch
#define TT 512     // time / bucket_size
#define NU 256     // units
#define N3 768     // 3*units
#define LN_EPS 1e-5f

typedef unsigned long long ull;
typedef unsigned int uint;

// ---------------- scratch (static device arrays; no runtime allocation) ----
__device__ float g_xemb[TT * BB * NU];   // [t][b][c]   33.5 MB
__device__ float g_s1[TT * BB * N3];     // [t][b][768] 100 MB (LN'd in place)
__device__ uint  g_enc[BB * NU];         // encoded running max for conv

// ---------------- small helpers -------------------------------------------
__device__ __forceinline__ uint enc_f(float v) {
    uint u = __float_as_uint(v);
    return ((int)u < 0) ? ~u : (u | 0x80000000u);
}
__device__ __forceinline__ float dec_f(uint e) {
    uint u = (e & 0x80000000u) ? (e ^ 0x80000000u) : ~e;
    return __uint_as_float(u);
}
__device__ __forceinline__ float hsig(float v) {
    return fminf(fmaxf(0.2f * v + 0.5f, 0.0f), 1.0f);
}
__device__ __forceinline__ float2 ull2f2(ull v) {
    float2 r;
    asm("mov.b64 {%0, %1}, %2;" : "=f"(r.x), "=f"(r.y) : "l"(v));
    return r;
}
__device__ __forceinline__ ull f22ull(float2 v) {
    ull r;
    asm("mov.b64 %0, {%1, %2};" : "=l"(r) : "f"(v.x), "f"(v.y));
    return r;
}
// packed fma: acc.{lo,hi} += hk.{lo,hi} * u
#define FMA2(acc, hk, uval) do {                                          \
    ull _pu;                                                              \
    asm("mov.b64 %0, {%1, %1};" : "=l"(_pu) : "f"(uval));                 \
    asm("fma.rn.f32x2 %0, %1, %2, %0;" : "+l"(acc) : "l"(hk), "l"(_pu));  \
} while (0)

__device__ __forceinline__ uint ctarank() {
    uint r; asm("mov.u32 %0, %%cluster_ctarank;" : "=r"(r)); return r;
}
__device__ __forceinline__ void st_cl_b64(void* laddr, uint r, ull v) {
    uint la = (uint)__cvta_generic_to_shared(laddr);
    asm volatile(
        "{ .reg .b32 ra; mapa.shared::cluster.u32 ra, %0, %1; "
        "st.shared::cluster.b64 [ra], %2; }"
        :: "r"(la), "r"(r), "l"(v) : "memory");
}
#define CLUSTER_SYNC() do {                                        \
    asm volatile("barrier.cluster.arrive.aligned;" ::: "memory");  \
    asm volatile("barrier.cluster.wait.aligned;" ::: "memory");    \
} while (0)

// bf16x3 split: pack two consecutive-k fp32 values into {hiPair, midPair}.
__device__ __forceinline__ uint2 bf16x3_pack(float va, float vb) {
    __nv_bfloat16 ha = __float2bfloat16(va);
    __nv_bfloat16 hb = __float2bfloat16(vb);
    float ra = va - __bfloat162float(ha);
    float rb = vb - __bfloat162float(hb);
    __nv_bfloat16 ma = __float2bfloat16(ra);
    __nv_bfloat16 mb = __float2bfloat16(rb);
    uint hi  = ((uint)__bfloat16_as_ushort(hb) << 16) |
               (uint)__bfloat16_as_ushort(ha);
    uint mid = ((uint)__bfloat16_as_ushort(mb) << 16) |
               (uint)__bfloat16_as_ushort(ma);
    return make_uint2(hi, mid);
}

#define MMA_BF16(cc, a0, a1, a2, a3, b0, b1)                              \
    asm("mma.sync.aligned.m16n8k16.row.col.f32.bf16.bf16.f32 "            \
        "{%0,%1,%2,%3}, {%4,%5,%6,%7}, {%8,%9}, {%0,%1,%2,%3};"           \
        : "+f"(cc[0]), "+f"(cc[1]), "+f"(cc[2]), "+f"(cc[3])              \
        : "r"(a0), "r"(a1), "r"(a2), "r"(a3), "r"(b0), "r"(b1))

// ---------------- embedding gather (+ g_enc init fused) --------------------
__global__ void embed_kernel(const int* __restrict__ x,
                             const float* __restrict__ emb) {
    int idx = blockIdx.x * 256 + threadIdx.x;
    int c = idx & 255;
    int b = (idx >> 8) & 63;
    int t = idx >> 14;
    int row = x[(size_t)b * TT + t];
    g_xemb[idx] = emb[(size_t)row * NU + c];
    if (blockIdx.x < 64)
        g_enc[blockIdx.x * 256 + threadIdx.x] = enc_f(-INFINITY);
}

__global__ void decode_kernel(float* __restrict__ out) {
    int f = threadIdx.x;           // 256
    int b = blockIdx.x;            // 64
    out[(size_t)b * 512 + 256 + f] = dec_f(g_enc[b * 256 + f]);
}

// ---------------- 128x128 bf16x3 tensor-core GEMM (R12-proven) -------------
#define AST2 132
#define GTB (8 * AST2)      // uint2 per tile (8 kpair rows x 132)
__global__ void __launch_bounds__(256)
gemm_tc(const float* __restrict__ A, const float* __restrict__ B,
        const float* __restrict__ bias, float* __restrict__ C,
        int N, int K, int domax) {
    extern __shared__ uint2 dsm2[];
    uint2* As2 = dsm2;               // [2][GTB]
    uint2* Bs2 = dsm2 + 2 * GTB;     // [2][GTB]

    int tid = threadIdx.x;
    int lane = tid & 31, warp = tid >> 5;
    int wm = warp >> 2, wn = warp & 3;           // warp grid 2x4
    int lk = lane & 3, lg = lane >> 2;
    int r0 = blockIdx.y * 128, c0 = blockIdx.x * 128;

    int am = tid >> 1, akq = (tid & 1) * 8;      // A: row am, 8 k's (4 pairs)
    int aRow0 = (tid & 1) * 4;                   // kpair row base for A stores
    int bkp = tid >> 5, bn4 = (tid & 31) * 4;    // B: kpair row bkp, 4 n's

    float c[4][4][4];
    #pragma unroll
    for (int i = 0; i < 4; i++)
        #pragma unroll
        for (int j = 0; j < 4; j++)
            #pragma unroll
            for (int q = 0; q < 4; q++) c[i][j][q] = 0.0f;

    const float* Arow = A + (size_t)(r0 + am) * 256;

    float aL[8], bL0[4], bL1[4];
    {   // prefetch tile 0
        int fk = akq;
        int ab = ((fk >> 8) << 14) + (fk & 255);
        float4 v0 = *(const float4*)&Arow[ab];
        float4 v1 = *(const float4*)&Arow[ab + 4];
        aL[0]=v0.x; aL[1]=v0.y; aL[2]=v0.z; aL[3]=v0.w;
        aL[4]=v1.x; aL[5]=v1.y; aL[6]=v1.z; aL[7]=v1.w;
        const float* Bp0 = &B[(size_t)(2 * bkp) * N + c0 + bn4];
        const float* Bp1 = Bp0 + N;
        float4 w0 = *(const float4*)Bp0;
        float4 w1 = *(const float4*)Bp1;
        bL0[0]=w0.x; bL0[1]=w0.y; bL0[2]=w0.z; bL0[3]=w0.w;
        bL1[0]=w1.x; bL1[1]=w1.y; bL1[2]=w1.z; bL1[3]=w1.w;
        #pragma unroll
        for (int j = 0; j < 4; j++) {
            As2[(aRow0 + j) * AST2 + am] = bf16x3_pack(aL[2*j], aL[2*j+1]);
            Bs2[bkp * AST2 + bn4 + j]    = bf16x3_pack(bL0[j], bL1[j]);
        }
    }
    __syncthreads();

    int buf = 0;
    for (int k0 = 0; k0 < K; k0 += 16) {
        bool more = (k0 + 16) < K;
        if (more) {
            int fk = k0 + 16 + akq;
            int ab = ((fk >> 8) << 14) + (fk & 255);
            float4 v0 = *(const float4*)&Arow[ab];
            float4 v1 = *(const float4*)&Arow[ab + 4];
            aL[0]=v0.x; aL[1]=v0.y; aL[2]=v0.z; aL[3]=v0.w;
            aL[4]=v1.x; aL[5]=v1.y; aL[6]=v1.z; aL[7]=v1.w;
            const float* Bp0 = &B[(size_t)(k0 + 16 + 2 * bkp) * N + c0 + bn4];
            const float* Bp1 = Bp0 + N;
            float4 w0 = *(const float4*)Bp0;
            float4 w1 = *(const float4*)Bp1;
            bL0[0]=w0.x; bL0[1]=w0.y; bL0[2]=w0.z; bL0[3]=w0.w;
            bL1[0]=w1.x; bL1[1]=w1.y; bL1[2]=w1.z; bL1[3]=w1.w;
        }
        const uint2* as2 = As2 + buf * GTB;
        const uint2* bs2 = Bs2 + buf * GTB;
        {
            uint afH[4][4], afM[4][4], bfH[4][2], bfM[4][2];
            #pragma unroll
            for (int mt = 0; mt < 4; mt++) {
                int m = wm * 64 + mt * 16 + lg;
                int i0 = lk * AST2 + m, i1 = (lk + 4) * AST2 + m;
                uint2 v0 = as2[i0], v1 = as2[i0 + 8];
                uint2 v2 = as2[i1], v3 = as2[i1 + 8];
                afH[mt][0] = v0.x; afM[mt][0] = v0.y;
                afH[mt][1] = v1.x; afM[mt][1] = v1.y;
                afH[mt][2] = v2.x; afM[mt][2] = v2.y;
                afH[mt][3] = v3.x; afM[mt][3] = v3.y;
            }
            #pragma unroll
            for (int nt = 0; nt < 4; nt++) {
                int n = wn * 32 + nt * 8 + lg;
                uint2 w0 = bs2[lk * AST2 + n];
                uint2 w1 = bs2[(lk + 4) * AST2 + n];
                bfH[nt][0] = w0.x; bfM[nt][0] = w0.y;
                bfH[nt][1] = w1.x; bfM[nt][1] = w1.y;
            }
            #pragma unroll
            for (int mt = 0; mt < 4; mt++)
                #pragma unroll
                for (int nt = 0; nt < 4; nt++) {
                    MMA_BF16(c[mt][nt], afM[mt][0], afM[mt][1], afM[mt][2],
                             afM[mt][3], bfH[nt][0], bfH[nt][1]);
                    MMA_BF16(c[mt][nt], afH[mt][0], afH[mt][1], afH[mt][2],
                             afH[mt][3], bfM[nt][0], bfM[nt][1]);
                    MMA_BF16(c[mt][nt], afH[mt][0], afH[mt][1], afH[mt][2],
                             afH[mt][3], bfH[nt][0], bfH[nt][1]);
                }
        }
        if (more) {
            uint2* aT = As2 + (buf ^ 1) * GTB;
            uint2* bT = Bs2 + (buf ^ 1) * GTB;
            #pragma unroll
            for (int j = 0; j < 4; j++) {
                aT[(aRow0 + j) * AST2 + am] = bf16x3_pack(aL[2*j], aL[2*j+1]);
                bT[bkp * AST2 + bn4 + j]    = bf16x3_pack(bL0[j], bL1[j]);
            }
        }
        __syncthreads();
        buf ^= 1;
    }

    // epilogue
    #pragma unroll
    for (int mt = 0; mt < 4; mt++) {
        #pragma unroll
        for (int nt = 0; nt < 4; nt++) {
            int row0 = r0 + wm * 64 + mt * 16 + lg;
            int col  = c0 + wn * 32 + nt * 8 + lk * 2;
            float v0 = c[mt][nt][0], v1 = c[mt][nt][1];
            float v2 = c[mt][nt][2], v3 = c[mt][nt][3];
            if (bias) {
                float bb0 = bias[col], bb1 = bias[col + 1];
                v0 += bb0; v1 += bb1; v2 += bb0; v3 += bb1;
            }
            if (C) {
                *(float2*)&C[(size_t)row0 * N + col] = make_float2(v0, v1);
                *(float2*)&C[(size_t)(row0 + 8) * N + col] = make_float2(v2, v3);
            }
            if (domax) {
                int ba = row0 & 63, bb = (row0 + 8) & 63;
                atomicMax(&g_enc[ba * 256 + col], enc_f(v0));
                atomicMax(&g_enc[ba * 256 + col + 1], enc_f(v1));
                atomicMax(&g_enc[bb * 256 + col], enc_f(v2));
                atomicMax(&g_enc[bb * 256 + col + 1], enc_f(v3));
            }
        }
    }
}

// ---------------- row LayerNorm over 768 cols, in place on g_s1 ------------
__global__ void ln_kernel(const float* __restrict__ gam,
                          const float* __restrict__ bet) {
    int row = blockIdx.x;
    float* p = g_s1 + (size_t)row * N3;
    int tid = threadIdx.x;
    float v0 = p[tid], v1 = p[tid + 256], v2 = p[tid + 512];
    float s = v0 + v1 + v2;
    float q = v0 * v0 + v1 * v1 + v2 * v2;
    __shared__ float rs[8], rq[8];
    __shared__ float tot[2];
    int lane = tid & 31, w = tid >> 5;
    #pragma unroll
    for (int o = 16; o; o >>= 1) {
        s += __shfl_down_sync(0xffffffffu, s, o);
        q += __shfl_down_sync(0xffffffffu, q, o);
    }
    if (!lane) { rs[w] = s; rq[w] = q; }
    __syncthreads();
    if (tid == 0) {
        float S = 0, Q = 0;
        for (int i = 0; i < 8; i++) { S += rs[i]; Q += rq[i]; }
        tot[0] = S; tot[1] = Q;
    }
    __syncthreads();
    float mean = tot[0] * (1.0f / 768.0f);
    float var = fmaxf(tot[1] * (1.0f / 768.0f) - mean * mean, 0.0f);
    float inv = 1.0f / (sqrtf(var + LN_EPS) + LN_EPS);
    p[tid]       = gam[tid]       * ((v0 - mean) * inv) + bet[tid];
    p[tid + 256] = gam[tid + 256] * ((v1 - mean) * inv) + bet[tid + 256];
    p[tid + 512] = gam[tid + 512] * ((v2 - mean) * inv) + bet[tid + 512];
}

// =============== recurrence: 32 clusters x 4 CTAs, 2 syncs/step ============
// Phase A: as before (k-half per thread over 128 cols). S1 broadcasts LN-A
//   partials.
// Gate: z broadcast; rh stored LOCALLY (rank r owns units [64r,64r+64)).
// Phase B: each CTA computes the PARTIAL hc-presum over its own 64 k for
//   ALL 256 columns (1 col/thread), broadcasts partials. S2.
// Phase C: sum 4 rank partials -> full sB; LN-B reduction LOCALLY; h update
//   redundant in all CTAs. No third cluster sync.
__global__ void __launch_bounds__(256, 1) __cluster_dims__(4, 1, 1)
rec_kernel(const int* __restrict__ x, const float* __restrict__ Umat,
           const float* __restrict__ s1, const float* __restrict__ gammas,
           const float* __restrict__ betas, float* __restrict__ out) {
    __shared__ __align__(16) float2 h2[256];      // h, replicated
    __shared__ __align__(16) float2 rhl[64];      // rh, LOCAL (own units)
    __shared__ __align__(16) float2 z2g[256];     // z gates (broadcast)
    __shared__ __align__(16) float2 partHC[1024]; // [rank][col] hc partials
    __shared__ __align__(16) float2 cbuf[128];    // phase-A partial exchange
    __shared__ float2 wsl[16];                    // warp reduction slots
    __shared__ float2 pA[8];                      // LN-A partials per rank

    int tid  = threadIdx.x;
    uint rank = ctarank();
    int cid  = blockIdx.x >> 2;
    int b0   = cid * 2, b1 = b0 + 1;
    int lane = tid & 31, wid = tid >> 5;

    int colA  = tid & 127;
    int khalf = tid >> 7;
    int gA = (colA < 64) ? ((int)rank * 64 + colA)
                         : (256 + (int)rank * 64 + (colA - 64));
    float g1a = gammas[N3 + gA], be1a = betas[N3 + gA];
    int uC = tid;                                 // phase-B/C column (0..255)
    float g1c = gammas[N3 + 512 + uC], be1c = betas[N3 + 512 + uC];

    // ---- one-time: U slices into registers ----
    float UA[128];
    #pragma unroll
    for (int k = 0; k < 128; k++)
        UA[k] = Umat[(size_t)(khalf * 128 + k) * N3 + gA];
    // phase-B slice: rows [64*rank, 64*rank+64), column 512+tid
    float UB[64];
    #pragma unroll
    for (int j = 0; j < 64; j++)
        UB[j] = Umat[(size_t)((int)rank * 64 + j) * N3 + 512 + uC];

    h2[tid] = make_float2(0.0f, 0.0f);
    __syncthreads();
    CLUSTER_SYNC();

    for (int t = 0; t < TT; t++) {
        // prefetch s1 / masks (consumed late)
        const float* s1r0 = s1 + ((size_t)t * 64 + b0) * N3;
        const float* s1r1 = s1r0 + N3;
        float s1a0 = 0.0f, s1a1 = 0.0f;
        if (tid < 128) { s1a0 = s1r0[gA]; s1a1 = s1r1[gA]; }
        float s1c0 = s1r0[512 + uC], s1c1 = s1r1[512 + uC];
        int m0 = x[(size_t)b0 * TT + t], m1 = x[(size_t)b1 * TT + t];

        // ---- phase A: h @ U[:, gA] over k-half ----
        const ull* hp = (const ull*)h2 + khalf * 128;
        ull a0 = 0, a1 = 0, a2 = 0, a3 = 0;
        #pragma unroll
        for (int k = 0; k < 128; k += 4) {
            ulonglong2 ha = *(const ulonglong2*)(hp + k);
            ulonglong2 hb = *(const ulonglong2*)(hp + k + 2);
            FMA2(a0, ha.x, UA[k]);     FMA2(a1, ha.y, UA[k + 1]);
            FMA2(a2, hb.x, UA[k + 2]); FMA2(a3, hb.y, UA[k + 3]);
        }
        float2 f0 = ull2f2(a0), f1 = ull2f2(a1);
        float2 f2v = ull2f2(a2), f3 = ull2f2(a3);
        float2 accA = make_float2((f0.x + f1.x) + (f2v.x + f3.x),
                                  (f0.y + f1.y) + (f2v.y + f3.y));
        if (tid >= 128) cbuf[tid - 128] = accA;
        __syncthreads();

        float2 sval = make_float2(0.0f, 0.0f);
        if (tid < 128) {
            float2 oth = cbuf[tid];
            sval.x = accA.x + oth.x; sval.y = accA.y + oth.y;
            float p0 = sval.x, p1 = sval.y;
            float q0 = p0 * p0, q1 = p1 * p1;
            #pragma unroll
            for (int o = 16; o; o >>= 1) {
                p0 += __shfl_down_sync(0xffffffffu, p0, o);
                p1 += __shfl_down_sync(0xffffffffu, p1, o);
                q0 += __shfl_down_sync(0xffffffffu, q0, o);
                q1 += __shfl_down_sync(0xffffffffu, q1, o);
            }
            if (!lane) { wsl[wid] = make_float2(p0, p1);
                         wsl[8 + wid] = make_float2(q0, q1); }
        }
        __syncthreads();
        if (tid == 0) {
            float2 S = make_float2(0, 0), Q = make_float2(0, 0);
            #pragma unroll
            for (int w = 0; w < 4; w++) {
                S.x += wsl[w].x; S.y += wsl[w].y;
                Q.x += wsl[8 + w].x; Q.y += wsl[8 + w].y;
            }
            #pragma unroll
            for (uint r = 0; r < 4; r++) {
                st_cl_b64(&pA[rank], r, f22ull(S));
                st_cl_b64(&pA[4 + rank], r, f22ull(Q));
            }
        }
        CLUSTER_SYNC();   // S1: LN-A partials visible everywhere

        // ---- gate: z broadcast; rh LOCAL ----
        if (tid < 128) {
            float2 S = make_float2(0, 0), Q = make_float2(0, 0);
            #pragma unroll
            for (int r = 0; r < 4; r++) {
                S.x += pA[r].x; S.y += pA[r].y;
                Q.x += pA[4 + r].x; Q.y += pA[4 + r].y;
            }
            float mean0 = S.x * (1.0f / 512.0f), mean1 = S.y * (1.0f / 512.0f);
            float var0 = fmaxf(Q.x * (1.0f / 512.0f) - mean0 * mean0, 0.0f);
            float var1 = fmaxf(Q.y * (1.0f / 512.0f) - mean1 * mean1, 0.0f);
            float inv0 = 1.0f / (sqrtf(var0 + LN_EPS) + LN_EPS);
            float inv1 = 1.0f / (sqrtf(var1 + LN_EPS) + LN_EPS);
            float sv0 = hsig(s1a0 + g1a * ((sval.x - mean0) * inv0) + be1a);
            float sv1 = hsig(s1a1 + g1a * ((sval.y - mean1) * inv1) + be1a);
            if (colA < 64) {
                int gz = (int)rank * 64 + colA;
                ull pv = f22ull(make_float2(sv0, sv1));
                #pragma unroll
                for (uint r = 0; r < 4; r++) st_cl_b64(&z2g[gz], r, pv);
            } else {
                int uu = colA - 64;            // local unit index 0..63
                float2 h = h2[(int)rank * 64 + uu];
                rhl[uu] = make_float2(sv0 * h.x, sv1 * h.y);
            }
        }
        __syncthreads();   // rhl ready (local)

        // ---- phase B: partial (own rh slice) @ U[own 64 k, 512+uC] ----
        {
            const ull* rp = (const ull*)rhl;
            ull b0a = 0, b1a = 0;
            #pragma unroll
            for (int j = 0; j < 64; j += 4) {
                ulonglong2 ra = *(const ulonglong2*)(rp + j);
                ulonglong2 rb = *(const ulonglong2*)(rp + j + 2);
                FMA2(b0a, ra.x, UB[j]);     FMA2(b1a, ra.y, UB[j + 1]);
                FMA2(b0a, rb.x, UB[j + 2]); FMA2(b1a, rb.y, UB[j + 3]);
            }
            float2 g0 = ull2f2(b0a), g1 = ull2f2(b1a);
            float2 part = make_float2(g0.x + g1.x, g0.y + g1.y);
            ull pv = f22ull(part);
            #pragma unroll
            for (uint r = 0; r < 4; r++)
                st_cl_b64(&partHC[(int)rank * 256 + uC], r, pv);
        }
        CLUSTER_SYNC();   // S2: hc partials + z visible everywhere

        // ---- phase C: sum partials, LOCAL LN-B, gated update ----
        {
            float2 p0v = partHC[uC],        p1v = partHC[256 + uC];
            float2 p2v = partHC[512 + uC],  p3v = partHC[768 + uC];
            float2 sB = make_float2((p0v.x + p1v.x) + (p2v.x + p3v.x),
                                    (p0v.y + p1v.y) + (p2v.y + p3v.y));
            float p0 = sB.x, p1 = sB.y, q0 = p0 * p0, q1 = p1 * p1;
            #pragma unroll
            for (int o = 16; o; o >>= 1) {
                p0 += __shfl_down_sync(0xffffffffu, p0, o);
                p1 += __shfl_down_sync(0xffffffffu, p1, o);
                q0 += __shfl_down_sync(0xffffffffu, q0, o);
                q1 += __shfl_down_sync(0xffffffffu, q1, o);
            }
            if (!lane) { wsl[wid] = make_float2(p0, p1);
                         wsl[8 + wid] = make_float2(q0, q1); }
            __syncthreads();
            float2 S = make_float2(0, 0), Q = make_float2(0, 0);
            #pragma unroll
            for (int w = 0; w < 8; w++) {
                S.x += wsl[w].x; S.y += wsl[w].y;
                Q.x += wsl[8 + w].x; Q.y += wsl[8 + w].y;
            }
            float mean0 = S.x * (1.0f / 256.0f), mean1 = S.y * (1.0f / 256.0f);
            float var0 = fmaxf(Q.x * (1.0f / 256.0f) - mean0 * mean0, 0.0f);
            float var1 = fmaxf(Q.y * (1.0f / 256.0f) - mean1 * mean1, 0.0f);
            float inv0 = 1.0f / (sqrtf(var0 + LN_EPS) + LN_EPS);
            float inv1 = 1.0f / (sqrtf(var1 + LN_EPS) + LN_EPS);
            float hc0 = tanhf(s1c0 + g1c * ((sB.x - mean0) * inv0) + be1c);
            float hc1 = tanhf(s1c1 + g1c * ((sB.y - mean1) * inv1) + be1c);
            float2 z = z2g[uC];
            float2 h = h2[uC];
            float hn0 = z.x * h.x + (1.0f - z.x) * hc0;
            float hn1 = z.y * h.y + (1.0f - z.y) * hc1;
            h2[uC] = make_float2(m0 ? hn0 : h.x, m1 ? hn1 : h.y);
        }
        __syncthreads();   // h2 complete before next phase A (CTA-local)
    }

    if (rank == 0) {
        float2 h = h2[uC];
        out[(size_t)b0 * 512 + uC] = h.x;
        out[(size_t)b1 * 512 + uC] = h.y;
    }
}

// ---------------- launch ---------------------------------------------------
extern "C" void kernel_launch(void* const* d_in, const int* in_sizes, int n_in,
                              void* d_out, int out_size) {
    const int* x           = (const int*)d_in[0];   // token ids (int32)
    const float* emb       = (const float*)d_in[2];
    const float* W         = (const float*)d_in[3];
    const float* Umat      = (const float*)d_in[4];
    const float* bias      = (const float*)d_in[5];
    const float* gammas    = (const float*)d_in[6];
    const float* betas     = (const float*)d_in[7];
    const float* kern      = (const float*)d_in[8];
    float* out             = (float*)d_out;

    float *xe, *s1p;
    cudaGetSymbolAddress((void**)&xe, g_xemb);
    cudaGetSymbolAddress((void**)&s1p, g_s1);

    const int gsm = 4 * GTB * (int)sizeof(uint2);   // 33792 B
    cudaFuncSetAttribute(gemm_tc, cudaFuncAttributeMaxDynamicSharedMemorySize,
                         gsm);

    // 1) embedding gather (+ g_enc init fused)
    embed_kernel<<<TT * BB, 256>>>(x, emb);
    // 2) s1 = x_emb @ W + b  (M=32768, N=768, K=256), then LN in place
    gemm_tc<<<dim3(N3 / 128, TT * BB / 128), 256, gsm>>>(xe, W, bias, s1p,
                                                         N3, NU, 0);
    ln_kernel<<<TT * BB, 256>>>(gammas, betas);
    // 3) conv as ONE K=768 GEMM (M = 510*64 = 32640 = 255*128) with fused max
    gemm_tc<<<dim3(NU / 128, (510 * BB) / 128), 256, gsm>>>(xe, kern, nullptr,
                                                            nullptr, NU,
                                                            3 * NU, 1);
    decode_kernel<<<BB, 256>>>(out);
    // 4) recurrence: cluster-parallel, U register-resident, 2 syncs/step
    rec_kernel<<<128, 256>>>(x, Umat, s1p, gammas, betas, out);
}

// round 14
// speedup vs baseline: 1.7598x; 1.0158x over previous
#include <cuda_runtime.h>
#include <cuda_bf16.h>
#include <math.h>

// Problem constants (fixed shapes)
#define BB 64      // batch
#define TT 512     // time / bucket_size
#define NU 256     // units
#define N3 768     // 3*units
#define LN_EPS 1e-5f

typedef unsigned long long ull;
typedef unsigned int uint;

// ---------------- scratch (static device arrays; no runtime allocation) ----
__device__ uint2 g_xembp[TT * BB * 128];   // packed bf16 hi/mid, kpair-major
__device__ float g_s1[TT * BB * N3];       // [t][b][768] (LN'd in place)
__device__ uint  g_enc[BB * NU];           // encoded running max for conv
__device__ uint2 g_Wp[128 * N3];           // W packed: 128 kpair x 768
__device__ uint2 g_Kp[384 * NU];           // kern packed: 384 kpair x 256

// ---------------- small helpers -------------------------------------------
__device__ __forceinline__ uint enc_f(float v) {
    uint u = __float_as_uint(v);
    return ((int)u < 0) ? ~u : (u | 0x80000000u);
}
__device__ __forceinline__ float dec_f(uint e) {
    uint u = (e & 0x80000000u) ? (e ^ 0x80000000u) : ~e;
    return __uint_as_float(u);
}
__device__ __forceinline__ float hsig(float v) {
    return fminf(fmaxf(0.2f * v + 0.5f, 0.0f), 1.0f);
}
__device__ __forceinline__ float2 ull2f2(ull v) {
    float2 r;
    asm("mov.b64 {%0, %1}, %2;" : "=f"(r.x), "=f"(r.y) : "l"(v));
    return r;
}
__device__ __forceinline__ ull f22ull(float2 v) {
    ull r;
    asm("mov.b64 %0, {%1, %2};" : "=l"(r) : "f"(v.x), "f"(v.y));
    return r;
}
// packed fma: acc.{lo,hi} += hk.{lo,hi} * u
#define FMA2(acc, hk, uval) do {                                          \
    ull _pu;                                                              \
    asm("mov.b64 %0, {%1, %1};" : "=l"(_pu) : "f"(uval));                 \
    asm("fma.rn.f32x2 %0, %1, %2, %0;" : "+l"(acc) : "l"(hk), "l"(_pu));  \
} while (0)

__device__ __forceinline__ uint ctarank() {
    uint r; asm("mov.u32 %0, %%cluster_ctarank;" : "=r"(r)); return r;
}
__device__ __forceinline__ void st_cl_b64(void* laddr, uint r, ull v) {
    uint la = (uint)__cvta_generic_to_shared(laddr);
    asm volatile(
        "{ .reg .b32 ra; mapa.shared::cluster.u32 ra, %0, %1; "
        "st.shared::cluster.b64 [ra], %2; }"
        :: "r"(la), "r"(r), "l"(v) : "memory");
}
#define CLUSTER_SYNC() do {                                        \
    asm volatile("barrier.cluster.arrive.aligned;" ::: "memory");  \
    asm volatile("barrier.cluster.wait.aligned;" ::: "memory");    \
} while (0)

// bf16x3 split: pack two consecutive-k fp32 values into {hiPair, midPair}.
__device__ __forceinline__ uint2 bf16x3_pack(float va, float vb) {
    __nv_bfloat16 ha = __float2bfloat16(va);
    __nv_bfloat16 hb = __float2bfloat16(vb);
    float ra = va - __bfloat162float(ha);
    float rb = vb - __bfloat162float(hb);
    __nv_bfloat16 ma = __float2bfloat16(ra);
    __nv_bfloat16 mb = __float2bfloat16(rb);
    uint hi  = ((uint)__bfloat16_as_ushort(hb) << 16) |
               (uint)__bfloat16_as_ushort(ha);
    uint mid = ((uint)__bfloat16_as_ushort(mb) << 16) |
               (uint)__bfloat16_as_ushort(ma);
    return make_uint2(hi, mid);
}

#define MMA_BF16(cc, a0, a1, a2, a3, b0, b1)                              \
    asm("mma.sync.aligned.m16n8k16.row.col.f32.bf16.bf16.f32 "            \
        "{%0,%1,%2,%3}, {%4,%5,%6,%7}, {%8,%9}, {%0,%1,%2,%3};"           \
        : "+f"(cc[0]), "+f"(cc[1]), "+f"(cc[2]), "+f"(cc[3])              \
        : "r"(a0), "r"(a1), "r"(a2), "r"(a3), "r"(b0), "r"(b1))

// ---------------- embedding gather: packed hi/mid output -------------------
// blockIdx.x = t*64+b, 128 threads; thread c2 packs channels 2c2, 2c2+1.
__global__ void embed_kernel(const int* __restrict__ x,
                             const float* __restrict__ emb) {
    int c2 = threadIdx.x;                  // 0..127
    int b = blockIdx.x & 63;
    int t = blockIdx.x >> 6;
    int row = x[(size_t)b * TT + t];
    float2 v = *(const float2*)&emb[(size_t)row * NU + 2 * c2];
    g_xembp[(size_t)blockIdx.x * 128 + c2] = bf16x3_pack(v.x, v.y);
    if (blockIdx.x < 128)
        g_enc[blockIdx.x * 128 + c2] = enc_f(-INFINITY);
}

// ---------------- prep: pack W and kern into kpair-major uint2 -------------
// grid 768 x 256: idx < 98304 -> W (128 kpair x 768), else kern (384 x 256).
__global__ void prep_kernel(const float* __restrict__ W,
                            const float* __restrict__ kern) {
    int idx = blockIdx.x * 256 + threadIdx.x;
    if (idx < 128 * N3) {
        int kp = idx / N3, n = idx - kp * N3;
        g_Wp[idx] = bf16x3_pack(W[(size_t)(2 * kp) * N3 + n],
                                W[(size_t)(2 * kp + 1) * N3 + n]);
    } else {
        int i = idx - 128 * N3;            // < 384*256
        int kp = i >> 8, n = i & 255;
        g_Kp[i] = bf16x3_pack(kern[(size_t)(2 * kp) * NU + n],
                              kern[(size_t)(2 * kp + 1) * NU + n]);
    }
}

__global__ void decode_kernel(float* __restrict__ out) {
    int f = threadIdx.x;           // 256
    int b = blockIdx.x;            // 64
    out[(size_t)b * 512 + 256 + f] = dec_f(g_enc[b * 256 + f]);
}

// ---------------- 128x128 bf16x3 tensor-core GEMM (pre-split inputs) -------
// A: packed uint2, segment addressing per kpair:
//   A2[row, kp] = A[row*128 + (kp>>7)*8192 + (kp&127)]  (plain when K=256;
//   width-3 conv as one GEMM when K=768).  B: packed kpair-major [K/2, N].
// Mainloop staging is pure copy: no CVT/pack math.
#define AST2 132
#define GTB (8 * AST2)      // uint2 per tile (8 kpair rows x 132)
__global__ void __launch_bounds__(256)
gemm_tc(const uint2* __restrict__ A, const uint2* __restrict__ B,
        const float* __restrict__ bias, float* __restrict__ C,
        int N, int K, int domax) {
    extern __shared__ uint2 dsm2[];
    uint2* As2 = dsm2;               // [2][GTB]
    uint2* Bs2 = dsm2 + 2 * GTB;     // [2][GTB]

    int tid = threadIdx.x;
    int lane = tid & 31, warp = tid >> 5;
    int wm = warp >> 2, wn = warp & 3;           // warp grid 2x4
    int lk = lane & 3, lg = lane >> 2;
    int r0 = blockIdx.y * 128, c0 = blockIdx.x * 128;

    // staging roles
    int am = tid >> 1, akp = (tid & 1) * 4;      // A: row am, 4 kpairs
    int bkp = tid >> 5, bn4 = (tid & 31) * 4;    // B: kpair row bkp, 4 n's

    float c[4][4][4];
    #pragma unroll
    for (int i = 0; i < 4; i++)
        #pragma unroll
        for (int j = 0; j < 4; j++)
            #pragma unroll
            for (int q = 0; q < 4; q++) c[i][j][q] = 0.0f;

    const uint2* Arow = A + (size_t)(r0 + am) * 128;

    uint4 aV0, aV1, bV0, bV1;
    {   // prefetch tile 0
        int kp = akp;
        int ab = ((kp >> 7) << 13) + (kp & 127);
        aV0 = *(const uint4*)&Arow[ab];
        aV1 = *(const uint4*)&Arow[ab + 2];
        const uint2* Bp = &B[(size_t)bkp * N + c0 + bn4];
        bV0 = *(const uint4*)Bp;
        bV1 = *(const uint4*)(Bp + 2);
        uint2* as = As2;
        as[(akp + 0) * AST2 + am] = make_uint2(aV0.x, aV0.y);
        as[(akp + 1) * AST2 + am] = make_uint2(aV0.z, aV0.w);
        as[(akp + 2) * AST2 + am] = make_uint2(aV1.x, aV1.y);
        as[(akp + 3) * AST2 + am] = make_uint2(aV1.z, aV1.w);
        *(uint4*)&Bs2[bkp * AST2 + bn4] = bV0;
        *(uint4*)&Bs2[bkp * AST2 + bn4 + 2] = bV1;
    }
    __syncthreads();

    int buf = 0;
    for (int k0 = 0; k0 < K; k0 += 16) {
        bool more = (k0 + 16) < K;
        if (more) {
            int kp = (k0 + 16) / 2 + akp;
            int ab = ((kp >> 7) << 13) + (kp & 127);
            aV0 = *(const uint4*)&Arow[ab];
            aV1 = *(const uint4*)&Arow[ab + 2];
            const uint2* Bp = &B[(size_t)((k0 + 16) / 2 + bkp) * N + c0 + bn4];
            bV0 = *(const uint4*)Bp;
            bV1 = *(const uint4*)(Bp + 2);
        }
        const uint2* as2 = As2 + buf * GTB;
        const uint2* bs2 = Bs2 + buf * GTB;
        {
            uint afH[4][4], afM[4][4], bfH[4][2], bfM[4][2];
            #pragma unroll
            for (int mt = 0; mt < 4; mt++) {
                int m = wm * 64 + mt * 16 + lg;
                int i0 = lk * AST2 + m, i1 = (lk + 4) * AST2 + m;
                uint2 v0 = as2[i0], v1 = as2[i0 + 8];
                uint2 v2 = as2[i1], v3 = as2[i1 + 8];
                afH[mt][0] = v0.x; afM[mt][0] = v0.y;
                afH[mt][1] = v1.x; afM[mt][1] = v1.y;
                afH[mt][2] = v2.x; afM[mt][2] = v2.y;
                afH[mt][3] = v3.x; afM[mt][3] = v3.y;
            }
            #pragma unroll
            for (int nt = 0; nt < 4; nt++) {
                int n = wn * 32 + nt * 8 + lg;
                uint2 w0 = bs2[lk * AST2 + n];
                uint2 w1 = bs2[(lk + 4) * AST2 + n];
                bfH[nt][0] = w0.x; bfM[nt][0] = w0.y;
                bfH[nt][1] = w1.x; bfM[nt][1] = w1.y;
            }
            #pragma unroll
            for (int mt = 0; mt < 4; mt++)
                #pragma unroll
                for (int nt = 0; nt < 4; nt++) {
                    MMA_BF16(c[mt][nt], afM[mt][0], afM[mt][1], afM[mt][2],
                             afM[mt][3], bfH[nt][0], bfH[nt][1]);
                    MMA_BF16(c[mt][nt], afH[mt][0], afH[mt][1], afH[mt][2],
                             afH[mt][3], bfM[nt][0], bfM[nt][1]);
                    MMA_BF16(c[mt][nt], afH[mt][0], afH[mt][1], afH[mt][2],
                             afH[mt][3], bfH[nt][0], bfH[nt][1]);
                }
        }
        if (more) {
            uint2* aT = As2 + (buf ^ 1) * GTB;
            uint2* bT = Bs2 + (buf ^ 1) * GTB;
            aT[(akp + 0) * AST2 + am] = make_uint2(aV0.x, aV0.y);
            aT[(akp + 1) * AST2 + am] = make_uint2(aV0.z, aV0.w);
            aT[(akp + 2) * AST2 + am] = make_uint2(aV1.x, aV1.y);
            aT[(akp + 3) * AST2 + am] = make_uint2(aV1.z, aV1.w);
            *(uint4*)&bT[bkp * AST2 + bn4] = bV0;
            *(uint4*)&bT[bkp * AST2 + bn4 + 2] = bV1;
        }
        __syncthreads();
        buf ^= 1;
    }

    // epilogue
    #pragma unroll
    for (int mt = 0; mt < 4; mt++) {
        #pragma unroll
        for (int nt = 0; nt < 4; nt++) {
            int row0 = r0 + wm * 64 + mt * 16 + lg;
            int col  = c0 + wn * 32 + nt * 8 + lk * 2;
            float v0 = c[mt][nt][0], v1 = c[mt][nt][1];
            float v2 = c[mt][nt][2], v3 = c[mt][nt][3];
            if (bias) {
                float bb0 = bias[col], bb1 = bias[col + 1];
                v0 += bb0; v1 += bb1; v2 += bb0; v3 += bb1;
            }
            if (C) {
                *(float2*)&C[(size_t)row0 * N + col] = make_float2(v0, v1);
                *(float2*)&C[(size_t)(row0 + 8) * N + col] = make_float2(v2, v3);
            }
            if (domax) {
                int ba = row0 & 63, bb = (row0 + 8) & 63;
                atomicMax(&g_enc[ba * 256 + col], enc_f(v0));
                atomicMax(&g_enc[ba * 256 + col + 1], enc_f(v1));
                atomicMax(&g_enc[bb * 256 + col], enc_f(v2));
                atomicMax(&g_enc[bb * 256 + col + 1], enc_f(v3));
            }
        }
    }
}

// ---------------- row LayerNorm over 768 cols, in place on g_s1 ------------
__global__ void ln_kernel(const float* __restrict__ gam,
                          const float* __restrict__ bet) {
    int row = blockIdx.x;
    float* p = g_s1 + (size_t)row * N3;
    int tid = threadIdx.x;
    float v0 = p[tid], v1 = p[tid + 256], v2 = p[tid + 512];
    float s = v0 + v1 + v2;
    float q = v0 * v0 + v1 * v1 + v2 * v2;
    __shared__ float rs[8], rq[8];
    __shared__ float tot[2];
    int lane = tid & 31, w = tid >> 5;
    #pragma unroll
    for (int o = 16; o; o >>= 1) {
        s += __shfl_down_sync(0xffffffffu, s, o);
        q += __shfl_down_sync(0xffffffffu, q, o);
    }
    if (!lane) { rs[w] = s; rq[w] = q; }
    __syncthreads();
    if (tid == 0) {
        float S = 0, Q = 0;
        for (int i = 0; i < 8; i++) { S += rs[i]; Q += rq[i]; }
        tot[0] = S; tot[1] = Q;
    }
    __syncthreads();
    float mean = tot[0] * (1.0f / 768.0f);
    float var = fmaxf(tot[1] * (1.0f / 768.0f) - mean * mean, 0.0f);
    float inv = 1.0f / (sqrtf(var + LN_EPS) + LN_EPS);
    p[tid]       = gam[tid]       * ((v0 - mean) * inv) + bet[tid];
    p[tid + 256] = gam[tid + 256] * ((v1 - mean) * inv) + bet[tid + 256];
    p[tid + 512] = gam[tid + 512] * ((v2 - mean) * inv) + bet[tid + 512];
}

// =============== recurrence: R13-proven, 2 cluster syncs/step ==============
__global__ void __launch_bounds__(256, 1) __cluster_dims__(4, 1, 1)
rec_kernel(const int* __restrict__ x, const float* __restrict__ Umat,
           const float* __restrict__ s1, const float* __restrict__ gammas,
           const float* __restrict__ betas, float* __restrict__ out) {
    __shared__ __align__(16) float2 h2[256];      // h, replicated
    __shared__ __align__(16) float2 rhl[64];      // rh, LOCAL (own units)
    __shared__ __align__(16) float2 z2g[256];     // z gates (broadcast)
    __shared__ __align__(16) float2 partHC[1024]; // [rank][col] hc partials
    __shared__ __align__(16) float2 cbuf[128];    // phase-A partial exchange
    __shared__ float2 wsl[16];                    // warp reduction slots
    __shared__ float2 pA[8];                      // LN-A partials per rank

    int tid  = threadIdx.x;
    uint rank = ctarank();
    int cid  = blockIdx.x >> 2;
    int b0   = cid * 2, b1 = b0 + 1;
    int lane = tid & 31, wid = tid >> 5;

    int colA  = tid & 127;
    int khalf = tid >> 7;
    int gA = (colA < 64) ? ((int)rank * 64 + colA)
                         : (256 + (int)rank * 64 + (colA - 64));
    float g1a = gammas[N3 + gA], be1a = betas[N3 + gA];
    int uC = tid;                                 // phase-B/C column (0..255)
    float g1c = gammas[N3 + 512 + uC], be1c = betas[N3 + 512 + uC];

    // ---- one-time: U slices into registers ----
    float UA[128];
    #pragma unroll
    for (int k = 0; k < 128; k++)
        UA[k] = Umat[(size_t)(khalf * 128 + k) * N3 + gA];
    float UB[64];
    #pragma unroll
    for (int j = 0; j < 64; j++)
        UB[j] = Umat[(size_t)((int)rank * 64 + j) * N3 + 512 + uC];

    h2[tid] = make_float2(0.0f, 0.0f);
    __syncthreads();
    CLUSTER_SYNC();

    for (int t = 0; t < TT; t++) {
        const float* s1r0 = s1 + ((size_t)t * 64 + b0) * N3;
        const float* s1r1 = s1r0 + N3;
        float s1a0 = 0.0f, s1a1 = 0.0f;
        if (tid < 128) { s1a0 = s1r0[gA]; s1a1 = s1r1[gA]; }
        float s1c0 = s1r0[512 + uC], s1c1 = s1r1[512 + uC];
        int m0 = x[(size_t)b0 * TT + t], m1 = x[(size_t)b1 * TT + t];

        // ---- phase A: h @ U[:, gA] over k-half ----
        const ull* hp = (const ull*)h2 + khalf * 128;
        ull a0 = 0, a1 = 0, a2 = 0, a3 = 0;
        #pragma unroll
        for (int k = 0; k < 128; k += 4) {
            ulonglong2 ha = *(const ulonglong2*)(hp + k);
            ulonglong2 hb = *(const ulonglong2*)(hp + k + 2);
            FMA2(a0, ha.x, UA[k]);     FMA2(a1, ha.y, UA[k + 1]);
            FMA2(a2, hb.x, UA[k + 2]); FMA2(a3, hb.y, UA[k + 3]);
        }
        float2 f0 = ull2f2(a0), f1 = ull2f2(a1);
        float2 f2v = ull2f2(a2), f3 = ull2f2(a3);
        float2 accA = make_float2((f0.x + f1.x) + (f2v.x + f3.x),
                                  (f0.y + f1.y) + (f2v.y + f3.y));
        if (tid >= 128) cbuf[tid - 128] = accA;
        __syncthreads();

        float2 sval = make_float2(0.0f, 0.0f);
        if (tid < 128) {
            float2 oth = cbuf[tid];
            sval.x = accA.x + oth.x; sval.y = accA.y + oth.y;
            float p0 = sval.x, p1 = sval.y;
            float q0 = p0 * p0, q1 = p1 * p1;
            #pragma unroll
            for (int o = 16; o; o >>= 1) {
                p0 += __shfl_down_sync(0xffffffffu, p0, o);
                p1 += __shfl_down_sync(0xffffffffu, p1, o);
                q0 += __shfl_down_sync(0xffffffffu, q0, o);
                q1 += __shfl_down_sync(0xffffffffu, q1, o);
            }
            if (!lane) { wsl[wid] = make_float2(p0, p1);
                         wsl[8 + wid] = make_float2(q0, q1); }
        }
        __syncthreads();
        if (tid == 0) {
            float2 S = make_float2(0, 0), Q = make_float2(0, 0);
            #pragma unroll
            for (int w = 0; w < 4; w++) {
                S.x += wsl[w].x; S.y += wsl[w].y;
                Q.x += wsl[8 + w].x; Q.y += wsl[8 + w].y;
            }
            #pragma unroll
            for (uint r = 0; r < 4; r++) {
                st_cl_b64(&pA[rank], r, f22ull(S));
                st_cl_b64(&pA[4 + rank], r, f22ull(Q));
            }
        }
        CLUSTER_SYNC();   // S1: LN-A partials visible everywhere

        // ---- gate: z broadcast; rh LOCAL ----
        if (tid < 128) {
            float2 S = make_float2(0, 0), Q = make_float2(0, 0);
            #pragma unroll
            for (int r = 0; r < 4; r++) {
                S.x += pA[r].x; S.y += pA[r].y;
                Q.x += pA[4 + r].x; Q.y += pA[4 + r].y;
            }
            float mean0 = S.x * (1.0f / 512.0f), mean1 = S.y * (1.0f / 512.0f);
            float var0 = fmaxf(Q.x * (1.0f / 512.0f) - mean0 * mean0, 0.0f);
            float var1 = fmaxf(Q.y * (1.0f / 512.0f) - mean1 * mean1, 0.0f);
            float inv0 = 1.0f / (sqrtf(var0 + LN_EPS) + LN_EPS);
            float inv1 = 1.0f / (sqrtf(var1 + LN_EPS) + LN_EPS);
            float sv0 = hsig(s1a0 + g1a * ((sval.x - mean0) * inv0) + be1a);
            float sv1 = hsig(s1a1 + g1a * ((sval.y - mean1) * inv1) + be1a);
            if (colA < 64) {
                int gz = (int)rank * 64 + colA;
                ull pv = f22ull(make_float2(sv0, sv1));
                #pragma unroll
                for (uint r = 0; r < 4; r++) st_cl_b64(&z2g[gz], r, pv);
            } else {
                int uu = colA - 64;
                float2 h = h2[(int)rank * 64 + uu];
                rhl[uu] = make_float2(sv0 * h.x, sv1 * h.y);
            }
        }
        __syncthreads();   // rhl ready (local)

        // ---- phase B: partial (own rh slice) @ U[own 64 k, 512+uC] ----
        {
            const ull* rp = (const ull*)rhl;
            ull b0a = 0, b1a = 0;
            #pragma unroll
            for (int j = 0; j < 64; j += 4) {
                ulonglong2 ra = *(const ulonglong2*)(rp + j);
                ulonglong2 rb = *(const ulonglong2*)(rp + j + 2);
                FMA2(b0a, ra.x, UB[j]);     FMA2(b1a, ra.y, UB[j + 1]);
                FMA2(b0a, rb.x, UB[j + 2]); FMA2(b1a, rb.y, UB[j + 3]);
            }
            float2 g0 = ull2f2(b0a), g1 = ull2f2(b1a);
            float2 part = make_float2(g0.x + g1.x, g0.y + g1.y);
            ull pv = f22ull(part);
            #pragma unroll
            for (uint r = 0; r < 4; r++)
                st_cl_b64(&partHC[(int)rank * 256 + uC], r, pv);
        }
        CLUSTER_SYNC();   // S2: hc partials + z visible everywhere

        // ---- phase C: sum partials, LOCAL LN-B, gated update ----
        {
            float2 p0v = partHC[uC],        p1v = partHC[256 + uC];
            float2 p2v = partHC[512 + uC],  p3v = partHC[768 + uC];
            float2 sB = make_float2((p0v.x + p1v.x) + (p2v.x + p3v.x),
                                    (p0v.y + p1v.y) + (p2v.y + p3v.y));
            float p0 = sB.x, p1 = sB.y, q0 = p0 * p0, q1 = p1 * p1;
            #pragma unroll
            for (int o = 16; o; o >>= 1) {
                p0 += __shfl_down_sync(0xffffffffu, p0, o);
                p1 += __shfl_down_sync(0xffffffffu, p1, o);
                q0 += __shfl_down_sync(0xffffffffu, q0, o);
                q1 += __shfl_down_sync(0xffffffffu, q1, o);
            }
            if (!lane) { wsl[wid] = make_float2(p0, p1);
                         wsl[8 + wid] = make_float2(q0, q1); }
            __syncthreads();
            float2 S = make_float2(0, 0), Q = make_float2(0, 0);
            #pragma unroll
            for (int w = 0; w < 8; w++) {
                S.x += wsl[w].x; S.y += wsl[w].y;
                Q.x += wsl[8 + w].x; Q.y += wsl[8 + w].y;
            }
            float mean0 = S.x * (1.0f / 256.0f), mean1 = S.y * (1.0f / 256.0f);
            float var0 = fmaxf(Q.x * (1.0f / 256.0f) - mean0 * mean0, 0.0f);
            float var1 = fmaxf(Q.y * (1.0f / 256.0f) - mean1 * mean1, 0.0f);
            float inv0 = 1.0f / (sqrtf(var0 + LN_EPS) + LN_EPS);
            float inv1 = 1.0f / (sqrtf(var1 + LN_EPS) + LN_EPS);
            float hc0 = tanhf(s1c0 + g1c * ((sB.x - mean0) * inv0) + be1c);
            float hc1 = tanhf(s1c1 + g1c * ((sB.y - mean1) * inv1) + be1c);
            float2 z = z2g[uC];
            float2 h = h2[uC];
            float hn0 = z.x * h.x + (1.0f - z.x) * hc0;
            float hn1 = z.y * h.y + (1.0f - z.y) * hc1;
            h2[uC] = make_float2(m0 ? hn0 : h.x, m1 ? hn1 : h.y);
        }
        __syncthreads();   // h2 complete before next phase A (CTA-local)
    }

    if (rank == 0) {
        float2 h = h2[uC];
        out[(size_t)b0 * 512 + uC] = h.x;
        out[(size_t)b1 * 512 + uC] = h.y;
    }
}

// ---------------- launch ---------------------------------------------------
extern "C" void kernel_launch(void* const* d_in, const int* in_sizes, int n_in,
                              void* d_out, int out_size) {
    const int* x           = (const int*)d_in[0];   // token ids (int32)
    const float* emb       = (const float*)d_in[2];
    const float* W         = (const float*)d_in[3];
    const float* Umat      = (const float*)d_in[4];
    const float* bias      = (const float*)d_in[5];
    const float* gammas    = (const float*)d_in[6];
    const float* betas     = (const float*)d_in[7];
    const float* kern      = (const float*)d_in[8];
    float* out             = (float*)d_out;

    uint2 *xep, *Wp, *Kp;
    float *s1p;
    cudaGetSymbolAddress((void**)&xep, g_xembp);
    cudaGetSymbolAddress((void**)&Wp, g_Wp);
    cudaGetSymbolAddress((void**)&Kp, g_Kp);
    cudaGetSymbolAddress((void**)&s1p, g_s1);

    const int gsm = 4 * GTB * (int)sizeof(uint2);   // 33792 B
    cudaFuncSetAttribute(gemm_tc, cudaFuncAttributeMaxDynamicSharedMemorySize,
                         gsm);

    // 1) embedding gather (packed) + weight packing + g_enc init
    embed_kernel<<<TT * BB, 128>>>(x, emb);
    prep_kernel<<<768, 256>>>(W, kern);
    // 2) s1 = x_emb @ W + b  (M=32768, N=768, K=256), then LN in place
    gemm_tc<<<dim3(N3 / 128, TT * BB / 128), 256, gsm>>>(xep, Wp, bias, s1p,
                                                         N3, NU, 0);
    ln_kernel<<<TT * BB, 256>>>(gammas, betas);
    // 3) conv as ONE K=768 GEMM (M = 510*64 = 32640 = 255*128) with fused max
    gemm_tc<<<dim3(NU / 128, (510 * BB) / 128), 256, gsm>>>(xep, Kp, nullptr,
                                                            nullptr, NU,
                                                            3 * NU, 1);
    decode_kernel<<<BB, 256>>>(out);
    // 4) recurrence: cluster-parallel, U register-resident, 2 syncs/step
    rec_kernel<<<128, 256>>>(x, Umat, s1p, gammas, betas, out);
}

// round 15
// speedup vs baseline: 1.7677x; 1.0045x over previous
#include <cuda_runtime.h>
#include <cuda_bf16.h>
#include <math.h>

// Problem constants (fixed shapes)
#define BB 64      // batch
#define TT 512     // time / bucket_size
#define NU 256     // units
#define N3 768     // 3*units
#define LN_EPS 1e-5f

typedef unsigned long long ull;
typedef unsigned int uint;

// ---------------- scratch (static device arrays; no runtime allocation) ----
__device__ uint2 g_xembp[TT * BB * 128];   // packed bf16 hi/mid, kpair-major
__device__ float g_s1[TT * BB * N3];       // [t][b][768] (LN'd in place)
__device__ uint  g_enc[BB * NU];           // encoded running max for conv
__device__ uint2 g_Wp[128 * N3];           // W packed: 128 kpair x 768
__device__ uint2 g_Kp[384 * NU];           // kern packed: 384 kpair x 256

// ---------------- small helpers -------------------------------------------
__device__ __forceinline__ uint enc_f(float v) {
    uint u = __float_as_uint(v);
    return ((int)u < 0) ? ~u : (u | 0x80000000u);
}
__device__ __forceinline__ float dec_f(uint e) {
    uint u = (e & 0x80000000u) ? (e ^ 0x80000000u) : ~e;
    return __uint_as_float(u);
}
__device__ __forceinline__ float hsig(float v) {
    return fminf(fmaxf(0.2f * v + 0.5f, 0.0f), 1.0f);
}
__device__ __forceinline__ float2 ull2f2(ull v) {
    float2 r;
    asm("mov.b64 {%0, %1}, %2;" : "=f"(r.x), "=f"(r.y) : "l"(v));
    return r;
}
__device__ __forceinline__ ull f22ull(float2 v) {
    ull r;
    asm("mov.b64 %0, {%1, %2};" : "=l"(r) : "f"(v.x), "f"(v.y));
    return r;
}
// raw packed fma: acc.{lo,hi} += a.{lo,hi} * b.{lo,hi}   (no duplication!)
#define FMA2R(acc, av, bv)                                                 \
    asm("fma.rn.f32x2 %0, %1, %2, %0;" : "+l"(acc) : "l"(av), "l"(bv))

__device__ __forceinline__ uint ctarank() {
    uint r; asm("mov.u32 %0, %%cluster_ctarank;" : "=r"(r)); return r;
}
__device__ __forceinline__ void st_cl_b64(void* laddr, uint r, ull v) {
    uint la = (uint)__cvta_generic_to_shared(laddr);
    asm volatile(
        "{ .reg .b32 ra; mapa.shared::cluster.u32 ra, %0, %1; "
        "st.shared::cluster.b64 [ra], %2; }"
        :: "r"(la), "r"(r), "l"(v) : "memory");
}
#define CLUSTER_SYNC() do {                                        \
    asm volatile("barrier.cluster.arrive.aligned;" ::: "memory");  \
    asm volatile("barrier.cluster.wait.aligned;" ::: "memory");    \
} while (0)

// bf16x3 split: pack two consecutive-k fp32 values into {hiPair, midPair}.
__device__ __forceinline__ uint2 bf16x3_pack(float va, float vb) {
    __nv_bfloat16 ha = __float2bfloat16(va);
    __nv_bfloat16 hb = __float2bfloat16(vb);
    float ra = va - __bfloat162float(ha);
    float rb = vb - __bfloat162float(hb);
    __nv_bfloat16 ma = __float2bfloat16(ra);
    __nv_bfloat16 mb = __float2bfloat16(rb);
    uint hi  = ((uint)__bfloat16_as_ushort(hb) << 16) |
               (uint)__bfloat16_as_ushort(ha);
    uint mid = ((uint)__bfloat16_as_ushort(mb) << 16) |
               (uint)__bfloat16_as_ushort(ma);
    return make_uint2(hi, mid);
}

#define MMA_BF16(cc, a0, a1, a2, a3, b0, b1)                              \
    asm("mma.sync.aligned.m16n8k16.row.col.f32.bf16.bf16.f32 "            \
        "{%0,%1,%2,%3}, {%4,%5,%6,%7}, {%8,%9}, {%0,%1,%2,%3};"           \
        : "+f"(cc[0]), "+f"(cc[1]), "+f"(cc[2]), "+f"(cc[3])              \
        : "r"(a0), "r"(a1), "r"(a2), "r"(a3), "r"(b0), "r"(b1))

// ---------------- embedding gather: packed hi/mid output -------------------
__global__ void embed_kernel(const int* __restrict__ x,
                             const float* __restrict__ emb) {
    int c2 = threadIdx.x;                  // 0..127
    int b = blockIdx.x & 63;
    int t = blockIdx.x >> 6;
    int row = x[(size_t)b * TT + t];
    float2 v = *(const float2*)&emb[(size_t)row * NU + 2 * c2];
    g_xembp[(size_t)blockIdx.x * 128 + c2] = bf16x3_pack(v.x, v.y);
    if (blockIdx.x < 128)
        g_enc[blockIdx.x * 128 + c2] = enc_f(-INFINITY);
}

// ---------------- prep: pack W and kern into kpair-major uint2 -------------
__global__ void prep_kernel(const float* __restrict__ W,
                            const float* __restrict__ kern) {
    int idx = blockIdx.x * 256 + threadIdx.x;
    if (idx < 128 * N3) {
        int kp = idx / N3, n = idx - kp * N3;
        g_Wp[idx] = bf16x3_pack(W[(size_t)(2 * kp) * N3 + n],
                                W[(size_t)(2 * kp + 1) * N3 + n]);
    } else {
        int i = idx - 128 * N3;            // < 384*256
        int kp = i >> 8, n = i & 255;
        g_Kp[i] = bf16x3_pack(kern[(size_t)(2 * kp) * NU + n],
                              kern[(size_t)(2 * kp + 1) * NU + n]);
    }
}

__global__ void decode_kernel(float* __restrict__ out) {
    int f = threadIdx.x;           // 256
    int b = blockIdx.x;            // 64
    out[(size_t)b * 512 + 256 + f] = dec_f(g_enc[b * 256 + f]);
}

// ---------------- 128x128 bf16x3 tensor-core GEMM (R14-proven) -------------
#define AST2 132
#define GTB (8 * AST2)      // uint2 per tile (8 kpair rows x 132)
__global__ void __launch_bounds__(256)
gemm_tc(const uint2* __restrict__ A, const uint2* __restrict__ B,
        const float* __restrict__ bias, float* __restrict__ C,
        int N, int K, int domax) {
    extern __shared__ uint2 dsm2[];
    uint2* As2 = dsm2;               // [2][GTB]
    uint2* Bs2 = dsm2 + 2 * GTB;     // [2][GTB]

    int tid = threadIdx.x;
    int lane = tid & 31, warp = tid >> 5;
    int wm = warp >> 2, wn = warp & 3;           // warp grid 2x4
    int lk = lane & 3, lg = lane >> 2;
    int r0 = blockIdx.y * 128, c0 = blockIdx.x * 128;

    int am = tid >> 1, akp = (tid & 1) * 4;      // A: row am, 4 kpairs
    int bkp = tid >> 5, bn4 = (tid & 31) * 4;    // B: kpair row bkp, 4 n's

    float c[4][4][4];
    #pragma unroll
    for (int i = 0; i < 4; i++)
        #pragma unroll
        for (int j = 0; j < 4; j++)
            #pragma unroll
            for (int q = 0; q < 4; q++) c[i][j][q] = 0.0f;

    const uint2* Arow = A + (size_t)(r0 + am) * 128;

    uint4 aV0, aV1, bV0, bV1;
    {   // prefetch tile 0
        int kp = akp;
        int ab = ((kp >> 7) << 13) + (kp & 127);
        aV0 = *(const uint4*)&Arow[ab];
        aV1 = *(const uint4*)&Arow[ab + 2];
        const uint2* Bp = &B[(size_t)bkp * N + c0 + bn4];
        bV0 = *(const uint4*)Bp;
        bV1 = *(const uint4*)(Bp + 2);
        uint2* as = As2;
        as[(akp + 0) * AST2 + am] = make_uint2(aV0.x, aV0.y);
        as[(akp + 1) * AST2 + am] = make_uint2(aV0.z, aV0.w);
        as[(akp + 2) * AST2 + am] = make_uint2(aV1.x, aV1.y);
        as[(akp + 3) * AST2 + am] = make_uint2(aV1.z, aV1.w);
        *(uint4*)&Bs2[bkp * AST2 + bn4] = bV0;
        *(uint4*)&Bs2[bkp * AST2 + bn4 + 2] = bV1;
    }
    __syncthreads();

    int buf = 0;
    for (int k0 = 0; k0 < K; k0 += 16) {
        bool more = (k0 + 16) < K;
        if (more) {
            int kp = (k0 + 16) / 2 + akp;
            int ab = ((kp >> 7) << 13) + (kp & 127);
            aV0 = *(const uint4*)&Arow[ab];
            aV1 = *(const uint4*)&Arow[ab + 2];
            const uint2* Bp = &B[(size_t)((k0 + 16) / 2 + bkp) * N + c0 + bn4];
            bV0 = *(const uint4*)Bp;
            bV1 = *(const uint4*)(Bp + 2);
        }
        const uint2* as2 = As2 + buf * GTB;
        const uint2* bs2 = Bs2 + buf * GTB;
        {
            uint afH[4][4], afM[4][4], bfH[4][2], bfM[4][2];
            #pragma unroll
            for (int mt = 0; mt < 4; mt++) {
                int m = wm * 64 + mt * 16 + lg;
                int i0 = lk * AST2 + m, i1 = (lk + 4) * AST2 + m;
                uint2 v0 = as2[i0], v1 = as2[i0 + 8];
                uint2 v2 = as2[i1], v3 = as2[i1 + 8];
                afH[mt][0] = v0.x; afM[mt][0] = v0.y;
                afH[mt][1] = v1.x; afM[mt][1] = v1.y;
                afH[mt][2] = v2.x; afM[mt][2] = v2.y;
                afH[mt][3] = v3.x; afM[mt][3] = v3.y;
            }
            #pragma unroll
            for (int nt = 0; nt < 4; nt++) {
                int n = wn * 32 + nt * 8 + lg;
                uint2 w0 = bs2[lk * AST2 + n];
                uint2 w1 = bs2[(lk + 4) * AST2 + n];
                bfH[nt][0] = w0.x; bfM[nt][0] = w0.y;
                bfH[nt][1] = w1.x; bfM[nt][1] = w1.y;
            }
            #pragma unroll
            for (int mt = 0; mt < 4; mt++)
                #pragma unroll
                for (int nt = 0; nt < 4; nt++) {
                    MMA_BF16(c[mt][nt], afM[mt][0], afM[mt][1], afM[mt][2],
                             afM[mt][3], bfH[nt][0], bfH[nt][1]);
                    MMA_BF16(c[mt][nt], afH[mt][0], afH[mt][1], afH[mt][2],
                             afH[mt][3], bfM[nt][0], bfM[nt][1]);
                    MMA_BF16(c[mt][nt], afH[mt][0], afH[mt][1], afH[mt][2],
                             afH[mt][3], bfH[nt][0], bfH[nt][1]);
                }
        }
        if (more) {
            uint2* aT = As2 + (buf ^ 1) * GTB;
            uint2* bT = Bs2 + (buf ^ 1) * GTB;
            aT[(akp + 0) * AST2 + am] = make_uint2(aV0.x, aV0.y);
            aT[(akp + 1) * AST2 + am] = make_uint2(aV0.z, aV0.w);
            aT[(akp + 2) * AST2 + am] = make_uint2(aV1.x, aV1.y);
            aT[(akp + 3) * AST2 + am] = make_uint2(aV1.z, aV1.w);
            *(uint4*)&bT[bkp * AST2 + bn4] = bV0;
            *(uint4*)&bT[bkp * AST2 + bn4 + 2] = bV1;
        }
        __syncthreads();
        buf ^= 1;
    }

    // epilogue
    #pragma unroll
    for (int mt = 0; mt < 4; mt++) {
        #pragma unroll
        for (int nt = 0; nt < 4; nt++) {
            int row0 = r0 + wm * 64 + mt * 16 + lg;
            int col  = c0 + wn * 32 + nt * 8 + lk * 2;
            float v0 = c[mt][nt][0], v1 = c[mt][nt][1];
            float v2 = c[mt][nt][2], v3 = c[mt][nt][3];
            if (bias) {
                float bb0 = bias[col], bb1 = bias[col + 1];
                v0 += bb0; v1 += bb1; v2 += bb0; v3 += bb1;
            }
            if (C) {
                *(float2*)&C[(size_t)row0 * N + col] = make_float2(v0, v1);
                *(float2*)&C[(size_t)(row0 + 8) * N + col] = make_float2(v2, v3);
            }
            if (domax) {
                int ba = row0 & 63, bb = (row0 + 8) & 63;
                atomicMax(&g_enc[ba * 256 + col], enc_f(v0));
                atomicMax(&g_enc[ba * 256 + col + 1], enc_f(v1));
                atomicMax(&g_enc[bb * 256 + col], enc_f(v2));
                atomicMax(&g_enc[bb * 256 + col + 1], enc_f(v3));
            }
        }
    }
}

// ---------------- row LayerNorm over 768 cols, in place on g_s1 ------------
__global__ void ln_kernel(const float* __restrict__ gam,
                          const float* __restrict__ bet) {
    int row = blockIdx.x;
    float* p = g_s1 + (size_t)row * N3;
    int tid = threadIdx.x;
    float v0 = p[tid], v1 = p[tid + 256], v2 = p[tid + 512];
    float s = v0 + v1 + v2;
    float q = v0 * v0 + v1 * v1 + v2 * v2;
    __shared__ float rs[8], rq[8];
    __shared__ float tot[2];
    int lane = tid & 31, w = tid >> 5;
    #pragma unroll
    for (int o = 16; o; o >>= 1) {
        s += __shfl_down_sync(0xffffffffu, s, o);
        q += __shfl_down_sync(0xffffffffu, q, o);
    }
    if (!lane) { rs[w] = s; rq[w] = q; }
    __syncthreads();
    if (tid == 0) {
        float S = 0, Q = 0;
        for (int i = 0; i < 8; i++) { S += rs[i]; Q += rq[i]; }
        tot[0] = S; tot[1] = Q;
    }
    __syncthreads();
    float mean = tot[0] * (1.0f / 768.0f);
    float var = fmaxf(tot[1] * (1.0f / 768.0f) - mean * mean, 0.0f);
    float inv = 1.0f / (sqrtf(var + LN_EPS) + LN_EPS);
    p[tid]       = gam[tid]       * ((v0 - mean) * inv) + bet[tid];
    p[tid + 256] = gam[tid + 256] * ((v1 - mean) * inv) + bet[tid + 256];
    p[tid + 512] = gam[tid + 512] * ((v2 - mean) * inv) + bet[tid + 512];
}

// =============== recurrence: 2 syncs/step, k-pair packed FMAs ==============
// h stored batch-separated (h0s, h1s) so (ull*)h naturally yields k-pairs;
// U pre-packed into ull pairs at init -> mainloop has ZERO MOV-duplication.
__global__ void __launch_bounds__(256, 1) __cluster_dims__(4, 1, 1)
rec_kernel(const int* __restrict__ x, const float* __restrict__ Umat,
           const float* __restrict__ s1, const float* __restrict__ gammas,
           const float* __restrict__ betas, float* __restrict__ out) {
    __shared__ __align__(16) float h0s[256];      // h batch row 0
    __shared__ __align__(16) float h1s[256];      // h batch row 1
    __shared__ __align__(16) float rhl0[64];      // rh local, batch 0
    __shared__ __align__(16) float rhl1[64];      // rh local, batch 1
    __shared__ __align__(16) float2 z2g[256];     // z gates (broadcast)
    __shared__ __align__(16) float2 partHC[1024]; // [rank][col] hc partials
    __shared__ __align__(16) float2 cbuf[128];    // phase-A partial exchange
    __shared__ float2 wsl[16];                    // warp reduction slots
    __shared__ float2 pA[8];                      // LN-A partials per rank

    int tid  = threadIdx.x;
    uint rank = ctarank();
    int cid  = blockIdx.x >> 2;
    int b0   = cid * 2, b1 = b0 + 1;
    int lane = tid & 31, wid = tid >> 5;

    int colA  = tid & 127;
    int khalf = tid >> 7;
    int gA = (colA < 64) ? ((int)rank * 64 + colA)
                         : (256 + (int)rank * 64 + (colA - 64));
    float g1a = gammas[N3 + gA], be1a = betas[N3 + gA];
    int uC = tid;                                 // phase-B/C column (0..255)
    float g1c = gammas[N3 + 512 + uC], be1c = betas[N3 + 512 + uC];

    // ---- one-time: U slices as k-pair-packed ull registers ----
    ull UAp[64];
    #pragma unroll
    for (int j = 0; j < 64; j++) {
        float ua = Umat[(size_t)(khalf * 128 + 2 * j) * N3 + gA];
        float ub = Umat[(size_t)(khalf * 128 + 2 * j + 1) * N3 + gA];
        UAp[j] = f22ull(make_float2(ua, ub));
    }
    ull UBp[32];
    #pragma unroll
    for (int j = 0; j < 32; j++) {
        float ua = Umat[(size_t)((int)rank * 64 + 2 * j) * N3 + 512 + uC];
        float ub = Umat[(size_t)((int)rank * 64 + 2 * j + 1) * N3 + 512 + uC];
        UBp[j] = f22ull(make_float2(ua, ub));
    }

    h0s[tid] = 0.0f; h1s[tid] = 0.0f;
    __syncthreads();
    CLUSTER_SYNC();

    for (int t = 0; t < TT; t++) {
        const float* s1r0 = s1 + ((size_t)t * 64 + b0) * N3;
        const float* s1r1 = s1r0 + N3;
        float s1a0 = 0.0f, s1a1 = 0.0f;
        if (tid < 128) { s1a0 = s1r0[gA]; s1a1 = s1r1[gA]; }
        float s1c0 = s1r0[512 + uC], s1c1 = s1r1[512 + uC];
        int m0 = x[(size_t)b0 * TT + t], m1 = x[(size_t)b1 * TT + t];

        // ---- phase A: h @ U[:, gA] over k-half (k-pair lanes) ----
        const ull* hp0 = (const ull*)h0s + khalf * 64;
        const ull* hp1 = (const ull*)h1s + khalf * 64;
        ull a00 = 0, a01 = 0, a10 = 0, a11 = 0;
        #pragma unroll
        for (int j = 0; j < 64; j += 2) {
            ulonglong2 v0 = *(const ulonglong2*)(hp0 + j);
            ulonglong2 v1 = *(const ulonglong2*)(hp1 + j);
            FMA2R(a00, v0.x, UAp[j]); FMA2R(a01, v0.y, UAp[j + 1]);
            FMA2R(a10, v1.x, UAp[j]); FMA2R(a11, v1.y, UAp[j + 1]);
        }
        float2 s00 = ull2f2(a00), s01 = ull2f2(a01);
        float2 s10 = ull2f2(a10), s11 = ull2f2(a11);
        float2 accA = make_float2((s00.x + s00.y) + (s01.x + s01.y),
                                  (s10.x + s10.y) + (s11.x + s11.y));
        if (tid >= 128) cbuf[tid - 128] = accA;
        __syncthreads();

        float2 sval = make_float2(0.0f, 0.0f);
        if (tid < 128) {
            float2 oth = cbuf[tid];
            sval.x = accA.x + oth.x; sval.y = accA.y + oth.y;
            float p0 = sval.x, p1 = sval.y;
            float q0 = p0 * p0, q1 = p1 * p1;
            #pragma unroll
            for (int o = 16; o; o >>= 1) {
                p0 += __shfl_down_sync(0xffffffffu, p0, o);
                p1 += __shfl_down_sync(0xffffffffu, p1, o);
                q0 += __shfl_down_sync(0xffffffffu, q0, o);
                q1 += __shfl_down_sync(0xffffffffu, q1, o);
            }
            if (!lane) { wsl[wid] = make_float2(p0, p1);
                         wsl[8 + wid] = make_float2(q0, q1); }
        }
        __syncthreads();
        if (tid == 0) {
            float2 S = make_float2(0, 0), Q = make_float2(0, 0);
            #pragma unroll
            for (int w = 0; w < 4; w++) {
                S.x += wsl[w].x; S.y += wsl[w].y;
                Q.x += wsl[8 + w].x; Q.y += wsl[8 + w].y;
            }
            #pragma unroll
            for (uint r = 0; r < 4; r++) {
                st_cl_b64(&pA[rank], r, f22ull(S));
                st_cl_b64(&pA[4 + rank], r, f22ull(Q));
            }
        }
        CLUSTER_SYNC();   // S1: LN-A partials visible everywhere

        // ---- gate: z broadcast; rh LOCAL ----
        if (tid < 128) {
            float2 S = make_float2(0, 0), Q = make_float2(0, 0);
            #pragma unroll
            for (int r = 0; r < 4; r++) {
                S.x += pA[r].x; S.y += pA[r].y;
                Q.x += pA[4 + r].x; Q.y += pA[4 + r].y;
            }
            float mean0 = S.x * (1.0f / 512.0f), mean1 = S.y * (1.0f / 512.0f);
            float var0 = fmaxf(Q.x * (1.0f / 512.0f) - mean0 * mean0, 0.0f);
            float var1 = fmaxf(Q.y * (1.0f / 512.0f) - mean1 * mean1, 0.0f);
            float inv0 = 1.0f / (sqrtf(var0 + LN_EPS) + LN_EPS);
            float inv1 = 1.0f / (sqrtf(var1 + LN_EPS) + LN_EPS);
            float sv0 = hsig(s1a0 + g1a * ((sval.x - mean0) * inv0) + be1a);
            float sv1 = hsig(s1a1 + g1a * ((sval.y - mean1) * inv1) + be1a);
            if (colA < 64) {
                int gz = (int)rank * 64 + colA;
                ull pv = f22ull(make_float2(sv0, sv1));
                #pragma unroll
                for (uint r = 0; r < 4; r++) st_cl_b64(&z2g[gz], r, pv);
            } else {
                int uu = colA - 64;
                int gu = (int)rank * 64 + uu;
                rhl0[uu] = sv0 * h0s[gu];
                rhl1[uu] = sv1 * h1s[gu];
            }
        }
        __syncthreads();   // rhl ready (local)

        // ---- phase B: partial (own rh slice) @ U[own 64 k, 512+uC] ----
        {
            const ull* rp0 = (const ull*)rhl0;
            const ull* rp1 = (const ull*)rhl1;
            ull b00 = 0, b01 = 0, b10 = 0, b11 = 0;
            #pragma unroll
            for (int j = 0; j < 32; j += 2) {
                ulonglong2 v0 = *(const ulonglong2*)(rp0 + j);
                ulonglong2 v1 = *(const ulonglong2*)(rp1 + j);
                FMA2R(b00, v0.x, UBp[j]); FMA2R(b01, v0.y, UBp[j + 1]);
                FMA2R(b10, v1.x, UBp[j]); FMA2R(b11, v1.y, UBp[j + 1]);
            }
            float2 t00 = ull2f2(b00), t01 = ull2f2(b01);
            float2 t10 = ull2f2(b10), t11 = ull2f2(b11);
            float2 part = make_float2((t00.x + t00.y) + (t01.x + t01.y),
                                      (t10.x + t10.y) + (t11.x + t11.y));
            ull pv = f22ull(part);
            #pragma unroll
            for (uint r = 0; r < 4; r++)
                st_cl_b64(&partHC[(int)rank * 256 + uC], r, pv);
        }
        CLUSTER_SYNC();   // S2: hc partials + z visible everywhere

        // ---- phase C: sum partials, LOCAL LN-B, gated update ----
        {
            float2 p0v = partHC[uC],        p1v = partHC[256 + uC];
            float2 p2v = partHC[512 + uC],  p3v = partHC[768 + uC];
            float2 sB = make_float2((p0v.x + p1v.x) + (p2v.x + p3v.x),
                                    (p0v.y + p1v.y) + (p2v.y + p3v.y));
            float p0 = sB.x, p1 = sB.y, q0 = p0 * p0, q1 = p1 * p1;
            #pragma unroll
            for (int o = 16; o; o >>= 1) {
                p0 += __shfl_down_sync(0xffffffffu, p0, o);
                p1 += __shfl_down_sync(0xffffffffu, p1, o);
                q0 += __shfl_down_sync(0xffffffffu, q0, o);
                q1 += __shfl_down_sync(0xffffffffu, q1, o);
            }
            if (!lane) { wsl[wid] = make_float2(p0, p1);
                         wsl[8 + wid] = make_float2(q0, q1); }
            __syncthreads();
            float2 S = make_float2(0, 0), Q = make_float2(0, 0);
            #pragma unroll
            for (int w = 0; w < 8; w++) {
                S.x += wsl[w].x; S.y += wsl[w].y;
                Q.x += wsl[8 + w].x; Q.y += wsl[8 + w].y;
            }
            float mean0 = S.x * (1.0f / 256.0f), mean1 = S.y * (1.0f / 256.0f);
            float var0 = fmaxf(Q.x * (1.0f / 256.0f) - mean0 * mean0, 0.0f);
            float var1 = fmaxf(Q.y * (1.0f / 256.0f) - mean1 * mean1, 0.0f);
            float inv0 = 1.0f / (sqrtf(var0 + LN_EPS) + LN_EPS);
            float inv1 = 1.0f / (sqrtf(var1 + LN_EPS) + LN_EPS);
            float hc0 = tanhf(s1c0 + g1c * ((sB.x - mean0) * inv0) + be1c);
            float hc1 = tanhf(s1c1 + g1c * ((sB.y - mean1) * inv1) + be1c);
            float2 z = z2g[uC];
            float h0 = h0s[uC], h1 = h1s[uC];
            float hn0 = z.x * h0 + (1.0f - z.x) * hc0;
            float hn1 = z.y * h1 + (1.0f - z.y) * hc1;
            h0s[uC] = m0 ? hn0 : h0;
            h1s[uC] = m1 ? hn1 : h1;
        }
        __syncthreads();   // h complete before next phase A (CTA-local)
    }

    if (rank == 0) {
        out[(size_t)b0 * 512 + uC] = h0s[uC];
        out[(size_t)b1 * 512 + uC] = h1s[uC];
    }
}

// ---------------- launch ---------------------------------------------------
extern "C" void kernel_launch(void* const* d_in, const int* in_sizes, int n_in,
                              void* d_out, int out_size) {
    const int* x           = (const int*)d_in[0];   // token ids (int32)
    const float* emb       = (const float*)d_in[2];
    const float* W         = (const float*)d_in[3];
    const float* Umat      = (const float*)d_in[4];
    const float* bias      = (const float*)d_in[5];
    const float* gammas    = (const float*)d_in[6];
    const float* betas     = (const float*)d_in[7];
    const float* kern      = (const float*)d_in[8];
    float* out             = (float*)d_out;

    uint2 *xep, *Wp, *Kp;
    float *s1p;
    cudaGetSymbolAddress((void**)&xep, g_xembp);
    cudaGetSymbolAddress((void**)&Wp, g_Wp);
    cudaGetSymbolAddress((void**)&Kp, g_Kp);
    cudaGetSymbolAddress((void**)&s1p, g_s1);

    const int gsm = 4 * GTB * (int)sizeof(uint2);   // 33792 B
    cudaFuncSetAttribute(gemm_tc, cudaFuncAttributeMaxDynamicSharedMemorySize,
                         gsm);

    // 1) embedding gather (packed) + weight packing + g_enc init
    embed_kernel<<<TT * BB, 128>>>(x, emb);
    prep_kernel<<<768, 256>>>(W, kern);
    // 2) s1 = x_emb @ W + b  (M=32768, N=768, K=256), then LN in place
    gemm_tc<<<dim3(N3 / 128, TT * BB / 128), 256, gsm>>>(xep, Wp, bias, s1p,
                                                         N3, NU, 0);
    ln_kernel<<<TT * BB, 256>>>(gammas, betas);
    // 3) conv as ONE K=768 GEMM (M = 510*64 = 32640 = 255*128) with fused max
    gemm_tc<<<dim3(NU / 128, (510 * BB) / 128), 256, gsm>>>(xep, Kp, nullptr,
                                                            nullptr, NU,
                                                            3 * NU, 1);
    decode_kernel<<<BB, 256>>>(out);
    // 4) recurrence: cluster-parallel, k-pair packed, 2 syncs/step
    rec_kernel<<<128, 256>>>(x, Umat, s1p, gammas, betas, out);
}

// round 16
// speedup vs baseline: 1.8983x; 1.0739x over previous
#include <cuda_runtime.h>
#include <cuda_bf16.h>
#include <math.h>

// Problem constants (fixed shapes)
#define BB 64      // batch
#define TT 512     // time / bucket_size
#define NU 256     // units
#define N3 768     // 3*units
#define LN_EPS 1e-5f

typedef unsigned long long ull;
typedef unsigned int uint;

// ---------------- scratch (static device arrays; no runtime allocation) ----
__device__ uint2 g_xembp[TT * BB * 128];   // packed bf16 hi/mid, kpair-major
__device__ float g_s1[TT * BB * N3];       // [t][b][768] (LN'd in place)
__device__ uint  g_enc[BB * NU];           // encoded running max for conv
__device__ uint2 g_Wp[128 * N3];           // W packed: 128 kpair x 768
__device__ uint2 g_Kp[384 * NU];           // kern packed: 384 kpair x 256

// ---------------- small helpers -------------------------------------------
__device__ __forceinline__ uint enc_f(float v) {
    uint u = __float_as_uint(v);
    return ((int)u < 0) ? ~u : (u | 0x80000000u);
}
__device__ __forceinline__ float dec_f(uint e) {
    uint u = (e & 0x80000000u) ? (e ^ 0x80000000u) : ~e;
    return __uint_as_float(u);
}
__device__ __forceinline__ float hsig(float v) {
    return fminf(fmaxf(0.2f * v + 0.5f, 0.0f), 1.0f);
}
__device__ __forceinline__ float2 ull2f2(ull v) {
    float2 r;
    asm("mov.b64 {%0, %1}, %2;" : "=f"(r.x), "=f"(r.y) : "l"(v));
    return r;
}
__device__ __forceinline__ ull f22ull(float2 v) {
    ull r;
    asm("mov.b64 %0, {%1, %2};" : "=l"(r) : "f"(v.x), "f"(v.y));
    return r;
}
// raw packed fma: acc.{lo,hi} += a.{lo,hi} * b.{lo,hi}
#define FMA2R(acc, av, bv)                                                 \
    asm("fma.rn.f32x2 %0, %1, %2, %0;" : "+l"(acc) : "l"(av), "l"(bv))

__device__ __forceinline__ uint ctarank() {
    uint r; asm("mov.u32 %0, %%cluster_ctarank;" : "=r"(r)); return r;
}
__device__ __forceinline__ void st_cl_b64(void* laddr, uint r, ull v) {
    uint la = (uint)__cvta_generic_to_shared(laddr);
    asm volatile(
        "{ .reg .b32 ra; mapa.shared::cluster.u32 ra, %0, %1; "
        "st.shared::cluster.b64 [ra], %2; }"
        :: "r"(la), "r"(r), "l"(v) : "memory");
}
#define CLUSTER_SYNC() do {                                        \
    asm volatile("barrier.cluster.arrive.aligned;" ::: "memory");  \
    asm volatile("barrier.cluster.wait.aligned;" ::: "memory");    \
} while (0)

// bf16x3 split: pack two consecutive-k fp32 values into {hiPair, midPair}.
__device__ __forceinline__ uint2 bf16x3_pack(float va, float vb) {
    __nv_bfloat16 ha = __float2bfloat16(va);
    __nv_bfloat16 hb = __float2bfloat16(vb);
    float ra = va - __bfloat162float(ha);
    float rb = vb - __bfloat162float(hb);
    __nv_bfloat16 ma = __float2bfloat16(ra);
    __nv_bfloat16 mb = __float2bfloat16(rb);
    uint hi  = ((uint)__bfloat16_as_ushort(hb) << 16) |
               (uint)__bfloat16_as_ushort(ha);
    uint mid = ((uint)__bfloat16_as_ushort(mb) << 16) |
               (uint)__bfloat16_as_ushort(ma);
    return make_uint2(hi, mid);
}

#define MMA_BF16(cc, a0, a1, a2, a3, b0, b1)                              \
    asm("mma.sync.aligned.m16n8k16.row.col.f32.bf16.bf16.f32 "            \
        "{%0,%1,%2,%3}, {%4,%5,%6,%7}, {%8,%9}, {%0,%1,%2,%3};"           \
        : "+f"(cc[0]), "+f"(cc[1]), "+f"(cc[2]), "+f"(cc[3])              \
        : "r"(a0), "r"(a1), "r"(a2), "r"(a3), "r"(b0), "r"(b1))

// ---------------- embedding gather: packed hi/mid output -------------------
__global__ void embed_kernel(const int* __restrict__ x,
                             const float* __restrict__ emb) {
    int c2 = threadIdx.x;                  // 0..127
    int b = blockIdx.x & 63;
    int t = blockIdx.x >> 6;
    int row = x[(size_t)b * TT + t];
    float2 v = *(const float2*)&emb[(size_t)row * NU + 2 * c2];
    g_xembp[(size_t)blockIdx.x * 128 + c2] = bf16x3_pack(v.x, v.y);
    if (blockIdx.x < 128)
        g_enc[blockIdx.x * 128 + c2] = enc_f(-INFINITY);
}

// ---------------- prep: pack W and kern into kpair-major uint2 -------------
__global__ void prep_kernel(const float* __restrict__ W,
                            const float* __restrict__ kern) {
    int idx = blockIdx.x * 256 + threadIdx.x;
    if (idx < 128 * N3) {
        int kp = idx / N3, n = idx - kp * N3;
        g_Wp[idx] = bf16x3_pack(W[(size_t)(2 * kp) * N3 + n],
                                W[(size_t)(2 * kp + 1) * N3 + n]);
    } else {
        int i = idx - 128 * N3;            // < 384*256
        int kp = i >> 8, n = i & 255;
        g_Kp[i] = bf16x3_pack(kern[(size_t)(2 * kp) * NU + n],
                              kern[(size_t)(2 * kp + 1) * NU + n]);
    }
}

__global__ void decode_kernel(float* __restrict__ out) {
    int f = threadIdx.x;           // 256
    int b = blockIdx.x;            // 64
    out[(size_t)b * 512 + 256 + f] = dec_f(g_enc[b * 256 + f]);
}

// ---------------- 128x128 bf16x3 tensor-core GEMM (R14-proven) -------------
#define AST2 132
#define GTB (8 * AST2)      // uint2 per tile (8 kpair rows x 132)
__global__ void __launch_bounds__(256)
gemm_tc(const uint2* __restrict__ A, const uint2* __restrict__ B,
        const float* __restrict__ bias, float* __restrict__ C,
        int N, int K, int domax) {
    extern __shared__ uint2 dsm2[];
    uint2* As2 = dsm2;               // [2][GTB]
    uint2* Bs2 = dsm2 + 2 * GTB;     // [2][GTB]

    int tid = threadIdx.x;
    int lane = tid & 31, warp = tid >> 5;
    int wm = warp >> 2, wn = warp & 3;           // warp grid 2x4
    int lk = lane & 3, lg = lane >> 2;
    int r0 = blockIdx.y * 128, c0 = blockIdx.x * 128;

    int am = tid >> 1, akp = (tid & 1) * 4;      // A: row am, 4 kpairs
    int bkp = tid >> 5, bn4 = (tid & 31) * 4;    // B: kpair row bkp, 4 n's

    float c[4][4][4];
    #pragma unroll
    for (int i = 0; i < 4; i++)
        #pragma unroll
        for (int j = 0; j < 4; j++)
            #pragma unroll
            for (int q = 0; q < 4; q++) c[i][j][q] = 0.0f;

    const uint2* Arow = A + (size_t)(r0 + am) * 128;

    uint4 aV0, aV1, bV0, bV1;
    {   // prefetch tile 0
        int kp = akp;
        int ab = ((kp >> 7) << 13) + (kp & 127);
        aV0 = *(const uint4*)&Arow[ab];
        aV1 = *(const uint4*)&Arow[ab + 2];
        const uint2* Bp = &B[(size_t)bkp * N + c0 + bn4];
        bV0 = *(const uint4*)Bp;
        bV1 = *(const uint4*)(Bp + 2);
        uint2* as = As2;
        as[(akp + 0) * AST2 + am] = make_uint2(aV0.x, aV0.y);
        as[(akp + 1) * AST2 + am] = make_uint2(aV0.z, aV0.w);
        as[(akp + 2) * AST2 + am] = make_uint2(aV1.x, aV1.y);
        as[(akp + 3) * AST2 + am] = make_uint2(aV1.z, aV1.w);
        *(uint4*)&Bs2[bkp * AST2 + bn4] = bV0;
        *(uint4*)&Bs2[bkp * AST2 + bn4 + 2] = bV1;
    }
    __syncthreads();

    int buf = 0;
    for (int k0 = 0; k0 < K; k0 += 16) {
        bool more = (k0 + 16) < K;
        if (more) {
            int kp = (k0 + 16) / 2 + akp;
            int ab = ((kp >> 7) << 13) + (kp & 127);
            aV0 = *(const uint4*)&Arow[ab];
            aV1 = *(const uint4*)&Arow[ab + 2];
            const uint2* Bp = &B[(size_t)((k0 + 16) / 2 + bkp) * N + c0 + bn4];
            bV0 = *(const uint4*)Bp;
            bV1 = *(const uint4*)(Bp + 2);
        }
        const uint2* as2 = As2 + buf * GTB;
        const uint2* bs2 = Bs2 + buf * GTB;
        {
            uint afH[4][4], afM[4][4], bfH[4][2], bfM[4][2];
            #pragma unroll
            for (int mt = 0; mt < 4; mt++) {
                int m = wm * 64 + mt * 16 + lg;
                int i0 = lk * AST2 + m, i1 = (lk + 4) * AST2 + m;
                uint2 v0 = as2[i0], v1 = as2[i0 + 8];
                uint2 v2 = as2[i1], v3 = as2[i1 + 8];
                afH[mt][0] = v0.x; afM[mt][0] = v0.y;
                afH[mt][1] = v1.x; afM[mt][1] = v1.y;
                afH[mt][2] = v2.x; afM[mt][2] = v2.y;
                afH[mt][3] = v3.x; afM[mt][3] = v3.y;
            }
            #pragma unroll
            for (int nt = 0; nt < 4; nt++) {
                int n = wn * 32 + nt * 8 + lg;
                uint2 w0 = bs2[lk * AST2 + n];
                uint2 w1 = bs2[(lk + 4) * AST2 + n];
                bfH[nt][0] = w0.x; bfM[nt][0] = w0.y;
                bfH[nt][1] = w1.x; bfM[nt][1] = w1.y;
            }
            #pragma unroll
            for (int mt = 0; mt < 4; mt++)
                #pragma unroll
                for (int nt = 0; nt < 4; nt++) {
                    MMA_BF16(c[mt][nt], afM[mt][0], afM[mt][1], afM[mt][2],
                             afM[mt][3], bfH[nt][0], bfH[nt][1]);
                    MMA_BF16(c[mt][nt], afH[mt][0], afH[mt][1], afH[mt][2],
                             afH[mt][3], bfM[nt][0], bfM[nt][1]);
                    MMA_BF16(c[mt][nt], afH[mt][0], afH[mt][1], afH[mt][2],
                             afH[mt][3], bfH[nt][0], bfH[nt][1]);
                }
        }
        if (more) {
            uint2* aT = As2 + (buf ^ 1) * GTB;
            uint2* bT = Bs2 + (buf ^ 1) * GTB;
            aT[(akp + 0) * AST2 + am] = make_uint2(aV0.x, aV0.y);
            aT[(akp + 1) * AST2 + am] = make_uint2(aV0.z, aV0.w);
            aT[(akp + 2) * AST2 + am] = make_uint2(aV1.x, aV1.y);
            aT[(akp + 3) * AST2 + am] = make_uint2(aV1.z, aV1.w);
            *(uint4*)&bT[bkp * AST2 + bn4] = bV0;
            *(uint4*)&bT[bkp * AST2 + bn4 + 2] = bV1;
        }
        __syncthreads();
        buf ^= 1;
    }

    // epilogue
    #pragma unroll
    for (int mt = 0; mt < 4; mt++) {
        #pragma unroll
        for (int nt = 0; nt < 4; nt++) {
            int row0 = r0 + wm * 64 + mt * 16 + lg;
            int col  = c0 + wn * 32 + nt * 8 + lk * 2;
            float v0 = c[mt][nt][0], v1 = c[mt][nt][1];
            float v2 = c[mt][nt][2], v3 = c[mt][nt][3];
            if (bias) {
                float bb0 = bias[col], bb1 = bias[col + 1];
                v0 += bb0; v1 += bb1; v2 += bb0; v3 += bb1;
            }
            if (C) {
                *(float2*)&C[(size_t)row0 * N + col] = make_float2(v0, v1);
                *(float2*)&C[(size_t)(row0 + 8) * N + col] = make_float2(v2, v3);
            }
            if (domax) {
                int ba = row0 & 63, bb = (row0 + 8) & 63;
                atomicMax(&g_enc[ba * 256 + col], enc_f(v0));
                atomicMax(&g_enc[ba * 256 + col + 1], enc_f(v1));
                atomicMax(&g_enc[bb * 256 + col], enc_f(v2));
                atomicMax(&g_enc[bb * 256 + col + 1], enc_f(v3));
            }
        }
    }
}

// ---------------- row LayerNorm over 768 cols, in place on g_s1 ------------
__global__ void ln_kernel(const float* __restrict__ gam,
                          const float* __restrict__ bet) {
    int row = blockIdx.x;
    float* p = g_s1 + (size_t)row * N3;
    int tid = threadIdx.x;
    float v0 = p[tid], v1 = p[tid + 256], v2 = p[tid + 512];
    float s = v0 + v1 + v2;
    float q = v0 * v0 + v1 * v1 + v2 * v2;
    __shared__ float rs[8], rq[8];
    __shared__ float tot[2];
    int lane = tid & 31, w = tid >> 5;
    #pragma unroll
    for (int o = 16; o; o >>= 1) {
        s += __shfl_down_sync(0xffffffffu, s, o);
        q += __shfl_down_sync(0xffffffffu, q, o);
    }
    if (!lane) { rs[w] = s; rq[w] = q; }
    __syncthreads();
    if (tid == 0) {
        float S = 0, Q = 0;
        for (int i = 0; i < 8; i++) { S += rs[i]; Q += rq[i]; }
        tot[0] = S; tot[1] = Q;
    }
    __syncthreads();
    float mean = tot[0] * (1.0f / 768.0f);
    float var = fmaxf(tot[1] * (1.0f / 768.0f) - mean * mean, 0.0f);
    float inv = 1.0f / (sqrtf(var + LN_EPS) + LN_EPS);
    p[tid]       = gam[tid]       * ((v0 - mean) * inv) + bet[tid];
    p[tid + 256] = gam[tid + 256] * ((v1 - mean) * inv) + bet[tid + 256];
    p[tid + 512] = gam[tid + 512] * ((v2 - mean) * inv) + bet[tid + 512];
}

// =============== recurrence: R15-proven, + early PDL trigger ===============
__global__ void __launch_bounds__(256, 1) __cluster_dims__(4, 1, 1)
rec_kernel(const int* __restrict__ x, const float* __restrict__ Umat,
           const float* __restrict__ s1, const float* __restrict__ gammas,
           const float* __restrict__ betas, float* __restrict__ out) {
    // Let the PDL-dependent conv GEMM launch immediately: rec only touches
    // s1/h/U; conv touches g_xembp/g_Kp/g_enc (disjoint).
    asm volatile("griddepcontrol.launch_dependents;" ::: "memory");

    __shared__ __align__(16) float h0s[256];      // h batch row 0
    __shared__ __align__(16) float h1s[256];      // h batch row 1
    __shared__ __align__(16) float rhl0[64];      // rh local, batch 0
    __shared__ __align__(16) float rhl1[64];      // rh local, batch 1
    __shared__ __align__(16) float2 z2g[256];     // z gates (broadcast)
    __shared__ __align__(16) float2 partHC[1024]; // [rank][col] hc partials
    __shared__ __align__(16) float2 cbuf[128];    // phase-A partial exchange
    __shared__ float2 wsl[16];                    // warp reduction slots
    __shared__ float2 pA[8];                      // LN-A partials per rank

    int tid  = threadIdx.x;
    uint rank = ctarank();
    int cid  = blockIdx.x >> 2;
    int b0   = cid * 2, b1 = b0 + 1;
    int lane = tid & 31, wid = tid >> 5;

    int colA  = tid & 127;
    int khalf = tid >> 7;
    int gA = (colA < 64) ? ((int)rank * 64 + colA)
                         : (256 + (int)rank * 64 + (colA - 64));
    float g1a = gammas[N3 + gA], be1a = betas[N3 + gA];
    int uC = tid;                                 // phase-B/C column (0..255)
    float g1c = gammas[N3 + 512 + uC], be1c = betas[N3 + 512 + uC];

    // ---- one-time: U slices as k-pair-packed ull registers ----
    ull UAp[64];
    #pragma unroll
    for (int j = 0; j < 64; j++) {
        float ua = Umat[(size_t)(khalf * 128 + 2 * j) * N3 + gA];
        float ub = Umat[(size_t)(khalf * 128 + 2 * j + 1) * N3 + gA];
        UAp[j] = f22ull(make_float2(ua, ub));
    }
    ull UBp[32];
    #pragma unroll
    for (int j = 0; j < 32; j++) {
        float ua = Umat[(size_t)((int)rank * 64 + 2 * j) * N3 + 512 + uC];
        float ub = Umat[(size_t)((int)rank * 64 + 2 * j + 1) * N3 + 512 + uC];
        UBp[j] = f22ull(make_float2(ua, ub));
    }

    h0s[tid] = 0.0f; h1s[tid] = 0.0f;
    __syncthreads();
    CLUSTER_SYNC();

    for (int t = 0; t < TT; t++) {
        const float* s1r0 = s1 + ((size_t)t * 64 + b0) * N3;
        const float* s1r1 = s1r0 + N3;
        float s1a0 = 0.0f, s1a1 = 0.0f;
        if (tid < 128) { s1a0 = s1r0[gA]; s1a1 = s1r1[gA]; }
        float s1c0 = s1r0[512 + uC], s1c1 = s1r1[512 + uC];
        int m0 = x[(size_t)b0 * TT + t], m1 = x[(size_t)b1 * TT + t];

        // ---- phase A: h @ U[:, gA] over k-half (k-pair lanes) ----
        const ull* hp0 = (const ull*)h0s + khalf * 64;
        const ull* hp1 = (const ull*)h1s + khalf * 64;
        ull a00 = 0, a01 = 0, a10 = 0, a11 = 0;
        #pragma unroll
        for (int j = 0; j < 64; j += 2) {
            ulonglong2 v0 = *(const ulonglong2*)(hp0 + j);
            ulonglong2 v1 = *(const ulonglong2*)(hp1 + j);
            FMA2R(a00, v0.x, UAp[j]); FMA2R(a01, v0.y, UAp[j + 1]);
            FMA2R(a10, v1.x, UAp[j]); FMA2R(a11, v1.y, UAp[j + 1]);
        }
        float2 s00 = ull2f2(a00), s01 = ull2f2(a01);
        float2 s10 = ull2f2(a10), s11 = ull2f2(a11);
        float2 accA = make_float2((s00.x + s00.y) + (s01.x + s01.y),
                                  (s10.x + s10.y) + (s11.x + s11.y));
        if (tid >= 128) cbuf[tid - 128] = accA;
        __syncthreads();

        float2 sval = make_float2(0.0f, 0.0f);
        if (tid < 128) {
            float2 oth = cbuf[tid];
            sval.x = accA.x + oth.x; sval.y = accA.y + oth.y;
            float p0 = sval.x, p1 = sval.y;
            float q0 = p0 * p0, q1 = p1 * p1;
            #pragma unroll
            for (int o = 16; o; o >>= 1) {
                p0 += __shfl_down_sync(0xffffffffu, p0, o);
                p1 += __shfl_down_sync(0xffffffffu, p1, o);
                q0 += __shfl_down_sync(0xffffffffu, q0, o);
                q1 += __shfl_down_sync(0xffffffffu, q1, o);
            }
            if (!lane) { wsl[wid] = make_float2(p0, p1);
                         wsl[8 + wid] = make_float2(q0, q1); }
        }
        __syncthreads();
        if (tid == 0) {
            float2 S = make_float2(0, 0), Q = make_float2(0, 0);
            #pragma unroll
            for (int w = 0; w < 4; w++) {
                S.x += wsl[w].x; S.y += wsl[w].y;
                Q.x += wsl[8 + w].x; Q.y += wsl[8 + w].y;
            }
            #pragma unroll
            for (uint r = 0; r < 4; r++) {
                st_cl_b64(&pA[rank], r, f22ull(S));
                st_cl_b64(&pA[4 + rank], r, f22ull(Q));
            }
        }
        CLUSTER_SYNC();   // S1: LN-A partials visible everywhere

        // ---- gate: z broadcast; rh LOCAL ----
        if (tid < 128) {
            float2 S = make_float2(0, 0), Q = make_float2(0, 0);
            #pragma unroll
            for (int r = 0; r < 4; r++) {
                S.x += pA[r].x; S.y += pA[r].y;
                Q.x += pA[4 + r].x; Q.y += pA[4 + r].y;
            }
            float mean0 = S.x * (1.0f / 512.0f), mean1 = S.y * (1.0f / 512.0f);
            float var0 = fmaxf(Q.x * (1.0f / 512.0f) - mean0 * mean0, 0.0f);
            float var1 = fmaxf(Q.y * (1.0f / 512.0f) - mean1 * mean1, 0.0f);
            float inv0 = 1.0f / (sqrtf(var0 + LN_EPS) + LN_EPS);
            float inv1 = 1.0f / (sqrtf(var1 + LN_EPS) + LN_EPS);
            float sv0 = hsig(s1a0 + g1a * ((sval.x - mean0) * inv0) + be1a);
            float sv1 = hsig(s1a1 + g1a * ((sval.y - mean1) * inv1) + be1a);
            if (colA < 64) {
                int gz = (int)rank * 64 + colA;
                ull pv = f22ull(make_float2(sv0, sv1));
                #pragma unroll
                for (uint r = 0; r < 4; r++) st_cl_b64(&z2g[gz], r, pv);
            } else {
                int uu = colA - 64;
                int gu = (int)rank * 64 + uu;
                rhl0[uu] = sv0 * h0s[gu];
                rhl1[uu] = sv1 * h1s[gu];
            }
        }
        __syncthreads();   // rhl ready (local)

        // ---- phase B: partial (own rh slice) @ U[own 64 k, 512+uC] ----
        {
            const ull* rp0 = (const ull*)rhl0;
            const ull* rp1 = (const ull*)rhl1;
            ull b00 = 0, b01 = 0, b10 = 0, b11 = 0;
            #pragma unroll
            for (int j = 0; j < 32; j += 2) {
                ulonglong2 v0 = *(const ulonglong2*)(rp0 + j);
                ulonglong2 v1 = *(const ulonglong2*)(rp1 + j);
                FMA2R(b00, v0.x, UBp[j]); FMA2R(b01, v0.y, UBp[j + 1]);
                FMA2R(b10, v1.x, UBp[j]); FMA2R(b11, v1.y, UBp[j + 1]);
            }
            float2 t00 = ull2f2(b00), t01 = ull2f2(b01);
            float2 t10 = ull2f2(b10), t11 = ull2f2(b11);
            float2 part = make_float2((t00.x + t00.y) + (t01.x + t01.y),
                                      (t10.x + t10.y) + (t11.x + t11.y));
            ull pv = f22ull(part);
            #pragma unroll
            for (uint r = 0; r < 4; r++)
                st_cl_b64(&partHC[(int)rank * 256 + uC], r, pv);
        }
        CLUSTER_SYNC();   // S2: hc partials + z visible everywhere

        // ---- phase C: sum partials, LOCAL LN-B, gated update ----
        {
            float2 p0v = partHC[uC],        p1v = partHC[256 + uC];
            float2 p2v = partHC[512 + uC],  p3v = partHC[768 + uC];
            float2 sB = make_float2((p0v.x + p1v.x) + (p2v.x + p3v.x),
                                    (p0v.y + p1v.y) + (p2v.y + p3v.y));
            float p0 = sB.x, p1 = sB.y, q0 = p0 * p0, q1 = p1 * p1;
            #pragma unroll
            for (int o = 16; o; o >>= 1) {
                p0 += __shfl_down_sync(0xffffffffu, p0, o);
                p1 += __shfl_down_sync(0xffffffffu, p1, o);
                q0 += __shfl_down_sync(0xffffffffu, q0, o);
                q1 += __shfl_down_sync(0xffffffffu, q1, o);
            }
            if (!lane) { wsl[wid] = make_float2(p0, p1);
                         wsl[8 + wid] = make_float2(q0, q1); }
            __syncthreads();
            float2 S = make_float2(0, 0), Q = make_float2(0, 0);
            #pragma unroll
            for (int w = 0; w < 8; w++) {
                S.x += wsl[w].x; S.y += wsl[w].y;
                Q.x += wsl[8 + w].x; Q.y += wsl[8 + w].y;
            }
            float mean0 = S.x * (1.0f / 256.0f), mean1 = S.y * (1.0f / 256.0f);
            float var0 = fmaxf(Q.x * (1.0f / 256.0f) - mean0 * mean0, 0.0f);
            float var1 = fmaxf(Q.y * (1.0f / 256.0f) - mean1 * mean1, 0.0f);
            float inv0 = 1.0f / (sqrtf(var0 + LN_EPS) + LN_EPS);
            float inv1 = 1.0f / (sqrtf(var1 + LN_EPS) + LN_EPS);
            float hc0 = tanhf(s1c0 + g1c * ((sB.x - mean0) * inv0) + be1c);
            float hc1 = tanhf(s1c1 + g1c * ((sB.y - mean1) * inv1) + be1c);
            float2 z = z2g[uC];
            float h0 = h0s[uC], h1 = h1s[uC];
            float hn0 = z.x * h0 + (1.0f - z.x) * hc0;
            float hn1 = z.y * h1 + (1.0f - z.y) * hc1;
            h0s[uC] = m0 ? hn0 : h0;
            h1s[uC] = m1 ? hn1 : h1;
        }
        __syncthreads();   // h complete before next phase A (CTA-local)
    }

    if (rank == 0) {
        out[(size_t)b0 * 512 + uC] = h0s[uC];
        out[(size_t)b1 * 512 + uC] = h1s[uC];
    }
}

// ---------------- launch ---------------------------------------------------
extern "C" void kernel_launch(void* const* d_in, const int* in_sizes, int n_in,
                              void* d_out, int out_size) {
    const int* x           = (const int*)d_in[0];   // token ids (int32)
    const float* emb       = (const float*)d_in[2];
    const float* W         = (const float*)d_in[3];
    const float* Umat      = (const float*)d_in[4];
    const float* bias      = (const float*)d_in[5];
    const float* gammas    = (const float*)d_in[6];
    const float* betas     = (const float*)d_in[7];
    const float* kern      = (const float*)d_in[8];
    float* out             = (float*)d_out;

    uint2 *xep, *Wp, *Kp;
    float *s1p;
    cudaGetSymbolAddress((void**)&xep, g_xembp);
    cudaGetSymbolAddress((void**)&Wp, g_Wp);
    cudaGetSymbolAddress((void**)&Kp, g_Kp);
    cudaGetSymbolAddress((void**)&s1p, g_s1);

    const int gsm = 4 * GTB * (int)sizeof(uint2);   // 33792 B
    cudaFuncSetAttribute(gemm_tc, cudaFuncAttributeMaxDynamicSharedMemorySize,
                         gsm);

    // 1) embedding gather (packed) + weight packing + g_enc init
    embed_kernel<<<TT * BB, 128>>>(x, emb);
    prep_kernel<<<768, 256>>>(W, kern);
    // 2) s1 = x_emb @ W + b, then LN in place
    gemm_tc<<<dim3(N3 / 128, TT * BB / 128), 256, gsm>>>(xep, Wp, bias, s1p,
                                                         N3, NU, 0);
    ln_kernel<<<TT * BB, 256>>>(gammas, betas);
    // 3) recurrence (fires griddepcontrol.launch_dependents at entry)
    rec_kernel<<<128, 256>>>(x, Umat, s1p, gammas, betas, out);
    // 4) conv GEMM as PDL dependent of rec: starts immediately, fills the
    //    ~20 SMs rec leaves free, runs inside rec's ~1.4 ms shadow.
    {
        cudaLaunchConfig_t cfg = {};
        cfg.gridDim = dim3(NU / 128, (510 * BB) / 128);
        cfg.blockDim = dim3(256);
        cfg.dynamicSmemBytes = gsm;
        cfg.stream = 0;
        cudaLaunchAttribute at[1];
        at[0].id = cudaLaunchAttributeProgrammaticStreamSerialization;
        at[0].val.programmaticStreamSerializationAllowed = 1;
        cfg.attrs = at;
        cfg.numAttrs = 1;
        cudaLaunchKernelEx(&cfg, gemm_tc, (const uint2*)xep,
                           (const uint2*)Kp, (const float*)nullptr,
                           (float*)nullptr, (int)NU, (int)(3 * NU), 1);
    }
    // 5) decode (normal full-completion edge after conv)
    decode_kernel<<<BB, 256>>>(out);
}